// round 1
// baseline (speedup 1.0000x reference)
#include <cuda_runtime.h>
#include <cuda_bf16.h>

// Problem constants
#define BQ 8
#define NN 4096
#define CC 768
#define EE 768
#define MM (BQ * NN)     // 32768 tokens
#define QKVD (3 * EE)    // 2304

// Scratch (device globals; no allocation allowed)
__device__ float g_h[(size_t)MM * CC];        // 100 MB: ln(x), later ln(attn)
__device__ float g_qkv[(size_t)MM * QKVD];    // 302 MB: qkv, q/k normalized in place
__device__ float g_kvpart[32 * BQ * EE];      // partial kv sums (deterministic reduction)
__device__ float g_kv[BQ * EE];               // [B, E]

// ---------------------------------------------------------------------------
// Block-wide reduction of two floats across 256 threads.
// Valid result on warp 0 after return. Caller broadcasts via shared.
// ---------------------------------------------------------------------------
__device__ __forceinline__ void block_reduce2_256(float& a, float& b) {
    __shared__ float sa[8], sb[8];
    int lane = threadIdx.x & 31;
    int w = threadIdx.x >> 5;
#pragma unroll
    for (int o = 16; o > 0; o >>= 1) {
        a += __shfl_down_sync(0xffffffffu, a, o);
        b += __shfl_down_sync(0xffffffffu, b, o);
    }
    if (lane == 0) { sa[w] = a; sb[w] = b; }
    __syncthreads();
    if (w == 0) {
        a = (lane < 8) ? sa[lane] : 0.0f;
        b = (lane < 8) ? sb[lane] : 0.0f;
#pragma unroll
        for (int o = 4; o > 0; o >>= 1) {
            a += __shfl_down_sync(0xffu, a, o);
            b += __shfl_down_sync(0xffu, b, o);
        }
    }
}

// ---------------------------------------------------------------------------
// Kernel 1: h = layernorm(x) over C (eps 1e-5). One block (256 thr) per token.
// ---------------------------------------------------------------------------
__global__ __launch_bounds__(256) void k_ln_in(const float* __restrict__ x,
                                               const float* __restrict__ gam,
                                               const float* __restrict__ bet) {
    int t = blockIdx.x;
    int tid = threadIdx.x;
    const float* row = x + (size_t)t * CC;
    float v0 = row[tid], v1 = row[tid + 256], v2 = row[tid + 512];
    float s = v0 + v1 + v2;
    float sq = v0 * v0 + v1 * v1 + v2 * v2;
    block_reduce2_256(s, sq);
    __shared__ float s_mu, s_rstd;
    if (tid == 0) {
        float mu = s * (1.0f / CC);
        float var = sq * (1.0f / CC) - mu * mu;
        s_mu = mu;
        s_rstd = rsqrtf(var + 1e-5f);
    }
    __syncthreads();
    float mu = s_mu, rstd = s_rstd;
    float* out = g_h + (size_t)t * CC;
    out[tid]       = (v0 - mu) * rstd * gam[tid]       + bet[tid];
    out[tid + 256] = (v1 - mu) * rstd * gam[tid + 256] + bet[tid + 256];
    out[tid + 512] = (v2 - mu) * rstd * gam[tid + 512] + bet[tid + 512];
}

// ---------------------------------------------------------------------------
// SGEMM body: C[Mt,Nt] = A[Mt,K] @ B[K,Nt], row-major, 128x128 tile,
// 8x8 per thread, BK=16, global->register prefetch. All dims multiples of 128/16.
// ---------------------------------------------------------------------------
template <int Mt, int Nt, int K, int LDA, int LDB, int LDC>
__device__ __forceinline__ void sgemm_body(const float* __restrict__ A,
                                           const float* __restrict__ B,
                                           float* __restrict__ C) {
    __shared__ float As[16][128];
    __shared__ float Bs[16][128];

    int tid = threadIdx.x;
    int bm = blockIdx.y * 128;
    int bn = blockIdx.x * 128;
    int tx = tid & 15;   // 0..15 -> cols
    int ty = tid >> 4;   // 0..15 -> rows

    // A tile loads: 128 rows x 16 cols = 512 float4. Each thread: rows r, r+64.
    int arow = tid >> 2;          // 0..63
    int acol = (tid & 3) * 4;     // 0,4,8,12
    // B tile loads: 16 rows x 128 cols. Each thread: rows br, br+8.
    int brow = tid >> 5;          // 0..7
    int bcol = (tid & 31) * 4;    // 0..124

    const float* Ag0 = A + (size_t)(bm + arow) * LDA + acol;
    const float* Ag1 = A + (size_t)(bm + arow + 64) * LDA + acol;
    const float* Bg0 = B + (size_t)brow * LDB + bn + bcol;
    const float* Bg1 = B + (size_t)(brow + 8) * LDB + bn + bcol;

    float acc[8][8];
#pragma unroll
    for (int i = 0; i < 8; i++)
#pragma unroll
        for (int j = 0; j < 8; j++) acc[i][j] = 0.0f;

    float4 pa0 = *(const float4*)Ag0;
    float4 pa1 = *(const float4*)Ag1;
    float4 pb0 = *(const float4*)Bg0;
    float4 pb1 = *(const float4*)Bg1;

    // store tile 0
    As[acol + 0][arow] = pa0.x; As[acol + 1][arow] = pa0.y;
    As[acol + 2][arow] = pa0.z; As[acol + 3][arow] = pa0.w;
    As[acol + 0][arow + 64] = pa1.x; As[acol + 1][arow + 64] = pa1.y;
    As[acol + 2][arow + 64] = pa1.z; As[acol + 3][arow + 64] = pa1.w;
    *(float4*)&Bs[brow][bcol] = pb0;
    *(float4*)&Bs[brow + 8][bcol] = pb1;
    __syncthreads();

    const int ktiles = K / 16;
#pragma unroll 1
    for (int t = 0; t < ktiles; t++) {
        bool has_next = (t + 1 < ktiles);
        if (has_next) {
            pa0 = *(const float4*)(Ag0 + (t + 1) * 16);
            pa1 = *(const float4*)(Ag1 + (t + 1) * 16);
            pb0 = *(const float4*)(Bg0 + (size_t)(t + 1) * 16 * LDB);
            pb1 = *(const float4*)(Bg1 + (size_t)(t + 1) * 16 * LDB);
        }
#pragma unroll
        for (int kk = 0; kk < 16; kk++) {
            float4 a0 = *(const float4*)&As[kk][ty * 4];
            float4 a1 = *(const float4*)&As[kk][ty * 4 + 64];
            float4 b0 = *(const float4*)&Bs[kk][tx * 4];
            float4 b1 = *(const float4*)&Bs[kk][tx * 4 + 64];
            float ar[8] = {a0.x, a0.y, a0.z, a0.w, a1.x, a1.y, a1.z, a1.w};
            float br[8] = {b0.x, b0.y, b0.z, b0.w, b1.x, b1.y, b1.z, b1.w};
#pragma unroll
            for (int i = 0; i < 8; i++)
#pragma unroll
                for (int j = 0; j < 8; j++) acc[i][j] += ar[i] * br[j];
        }
        if (has_next) {
            __syncthreads();
            As[acol + 0][arow] = pa0.x; As[acol + 1][arow] = pa0.y;
            As[acol + 2][arow] = pa0.z; As[acol + 3][arow] = pa0.w;
            As[acol + 0][arow + 64] = pa1.x; As[acol + 1][arow + 64] = pa1.y;
            As[acol + 2][arow + 64] = pa1.z; As[acol + 3][arow + 64] = pa1.w;
            *(float4*)&Bs[brow][bcol] = pb0;
            *(float4*)&Bs[brow + 8][bcol] = pb1;
            __syncthreads();
        }
    }

#pragma unroll
    for (int i = 0; i < 8; i++) {
        int r = bm + ((i < 4) ? (ty * 4 + i) : (64 + ty * 4 + i - 4));
        float* crow = C + (size_t)r * LDC + bn;
        *(float4*)&crow[tx * 4] =
            make_float4(acc[i][0], acc[i][1], acc[i][2], acc[i][3]);
        *(float4*)&crow[tx * 4 + 64] =
            make_float4(acc[i][4], acc[i][5], acc[i][6], acc[i][7]);
    }
}

__global__ __launch_bounds__(256) void sgemm_qkv(const float* __restrict__ w) {
    sgemm_body<MM, QKVD, CC, CC, QKVD, QKVD>(g_h, w, g_qkv);
}
__global__ __launch_bounds__(256) void sgemm_proj(const float* __restrict__ w,
                                                  float* __restrict__ out) {
    sgemm_body<MM, CC, EE, EE, CC, CC>(g_h, w, out);
}

// ---------------------------------------------------------------------------
// Kernel 3: per-token L2 normalize q and k rows in place (eps 1e-12).
// ---------------------------------------------------------------------------
__global__ __launch_bounds__(256) void k_phi() {
    int t = blockIdx.x;
    int tid = threadIdx.x;
    float* qrow = g_qkv + (size_t)t * QKVD;
    float* krow = qrow + EE;
    float q0 = qrow[tid], q1 = qrow[tid + 256], q2 = qrow[tid + 512];
    float k0 = krow[tid], k1 = krow[tid + 256], k2 = krow[tid + 512];
    float sq = q0 * q0 + q1 * q1 + q2 * q2;
    float sk = k0 * k0 + k1 * k1 + k2 * k2;
    block_reduce2_256(sq, sk);
    __shared__ float s_iq, s_ik;
    if (tid == 0) {
        s_iq = 1.0f / fmaxf(sqrtf(sq), 1e-12f);
        s_ik = 1.0f / fmaxf(sqrtf(sk), 1e-12f);
    }
    __syncthreads();
    float iq = s_iq, ik = s_ik;
    qrow[tid] = q0 * iq; qrow[tid + 256] = q1 * iq; qrow[tid + 512] = q2 * iq;
    krow[tid] = k0 * ik; krow[tid + 256] = k1 * ik; krow[tid + 512] = k2 * ik;
}

// ---------------------------------------------------------------------------
// Kernel 4a: partial kv sums. Grid (32 token-chunks, B). Deterministic.
// ---------------------------------------------------------------------------
__global__ __launch_bounds__(256) void k_kvred() {
    int b = blockIdx.y;
    int chunk = blockIdx.x;     // 0..31, each 128 tokens
    int tid = threadIdx.x;
    float a0 = 0.f, a1 = 0.f, a2 = 0.f;
    int t0 = b * NN + chunk * 128;
    for (int i = 0; i < 128; i++) {
        const float* row = g_qkv + (size_t)(t0 + i) * QKVD;
        const float* kr = row + EE;
        const float* vr = row + 2 * EE;
        a0 += kr[tid] * vr[tid];
        a1 += kr[tid + 256] * vr[tid + 256];
        a2 += kr[tid + 512] * vr[tid + 512];
    }
    float* dst = g_kvpart + ((size_t)chunk * BQ + b) * EE;
    dst[tid] = a0; dst[tid + 256] = a1; dst[tid + 512] = a2;
}

// Kernel 4b: reduce 32 partials -> g_kv
__global__ __launch_bounds__(256) void k_kvsum() {
    int i = blockIdx.x * 256 + threadIdx.x;   // 0 .. B*E-1 (6144)
    float s = 0.f;
#pragma unroll
    for (int c = 0; c < 32; c++) s += g_kvpart[(size_t)c * BQ * EE + i];
    g_kv[i] = s;
}

// ---------------------------------------------------------------------------
// Kernel 5: attn = phi_q * kv[b]; layernorm over E -> g_h (reused).
// ---------------------------------------------------------------------------
__global__ __launch_bounds__(256) void k_attn_ln(const float* __restrict__ gam,
                                                 const float* __restrict__ bet) {
    int t = blockIdx.x;
    int b = t >> 12;            // t / 4096
    int tid = threadIdx.x;
    const float* qrow = g_qkv + (size_t)t * QKVD;   // phi_q in place
    const float* kvb = g_kv + b * EE;
    float a0 = qrow[tid] * kvb[tid];
    float a1 = qrow[tid + 256] * kvb[tid + 256];
    float a2 = qrow[tid + 512] * kvb[tid + 512];
    float s = a0 + a1 + a2;
    float sq = a0 * a0 + a1 * a1 + a2 * a2;
    block_reduce2_256(s, sq);
    __shared__ float s_mu, s_rstd;
    if (tid == 0) {
        float mu = s * (1.0f / EE);
        float var = sq * (1.0f / EE) - mu * mu;
        s_mu = mu;
        s_rstd = rsqrtf(var + 1e-5f);
    }
    __syncthreads();
    float mu = s_mu, rstd = s_rstd;
    float* out = g_h + (size_t)t * EE;
    out[tid]       = (a0 - mu) * rstd * gam[tid]       + bet[tid];
    out[tid + 256] = (a1 - mu) * rstd * gam[tid + 256] + bet[tid + 256];
    out[tid + 512] = (a2 - mu) * rstd * gam[tid + 512] + bet[tid + 512];
}

// ---------------------------------------------------------------------------
extern "C" void kernel_launch(void* const* d_in, const int* in_sizes, int n_in,
                              void* d_out, int out_size) {
    const float* x        = (const float*)d_in[0];
    const float* w_qkv    = (const float*)d_in[1];
    const float* w_proj   = (const float*)d_in[2];
    const float* ln_in_g  = (const float*)d_in[3];
    const float* ln_in_b  = (const float*)d_in[4];
    const float* ln_out_g = (const float*)d_in[5];
    const float* ln_out_b = (const float*)d_in[6];
    float* out = (float*)d_out;

    k_ln_in<<<MM, 256>>>(x, ln_in_g, ln_in_b);
    sgemm_qkv<<<dim3(QKVD / 128, MM / 128), 256>>>(w_qkv);
    k_phi<<<MM, 256>>>();
    k_kvred<<<dim3(32, BQ), 256>>>();
    k_kvsum<<<BQ * EE / 256, 256>>>();
    k_attn_ln<<<MM, 256>>>(ln_out_g, ln_out_b);
    sgemm_proj<<<dim3(CC / 128, MM / 128), 256>>>(w_proj, out);
}

// round 5
// speedup vs baseline: 1.7946x; 1.7946x over previous
#include <cuda_runtime.h>
#include <cuda_bf16.h>
#include <cstdint>

// Problem constants
#define BQ 8
#define NN 4096
#define CC 768
#define EE 768
#define MM (BQ * NN)     // 32768 tokens
#define QKVD (3 * EE)    // 2304

using bf16 = __nv_bfloat16;

// ---------------- device scratch (no allocation allowed) -------------------
__device__ __align__(128) float g_qkv[(size_t)MM * QKVD];   // GEMM1 out (fp32)
__device__ __align__(128) bf16  g_ahi[(size_t)MM * CC];     // A hi
__device__ __align__(128) bf16  g_alo[(size_t)MM * CC];     // A lo
__device__ __align__(128) bf16  g_bqhi[(size_t)QKVD * CC];  // w_qkv^T hi [2304,768]
__device__ __align__(128) bf16  g_bqlo[(size_t)QKVD * CC];
__device__ __align__(128) bf16  g_bphi[(size_t)EE * CC];    // w_proj^T hi [768,768]
__device__ __align__(128) bf16  g_bplo[(size_t)EE * CC];
__device__ float g_kvpart[32 * BQ * EE];
__device__ float g_kv[BQ * EE];
__device__ float g_qinv[MM];
__device__ float g_kinv[MM];

// ---------------------------- helpers --------------------------------------
__device__ __forceinline__ uint32_t smem_u32(const void* p) {
    uint32_t a;
    asm("{ .reg .u64 t; cvta.to.shared.u64 t, %1; cvt.u32.u64 %0, t; }"
        : "=r"(a) : "l"(p));
    return a;
}
__device__ __forceinline__ void cpa16(uint32_t dst, const void* src) {
    asm volatile("cp.async.cg.shared.global [%0], [%1], 16;" :: "r"(dst), "l"(src));
}
__device__ __forceinline__ void ldsm4(uint32_t* r, uint32_t addr) {
    asm volatile("ldmatrix.sync.aligned.m8n8.x4.shared.b16 {%0,%1,%2,%3}, [%4];"
                 : "=r"(r[0]), "=r"(r[1]), "=r"(r[2]), "=r"(r[3]) : "r"(addr));
}
__device__ __forceinline__ void mma_bf16(float* d, const uint32_t* a,
                                         const uint32_t* b) {
    asm volatile(
        "mma.sync.aligned.m16n8k16.row.col.f32.bf16.bf16.f32 "
        "{%0,%1,%2,%3},{%4,%5,%6,%7},{%8,%9},{%0,%1,%2,%3};"
        : "+f"(d[0]), "+f"(d[1]), "+f"(d[2]), "+f"(d[3])
        : "r"(a[0]), "r"(a[1]), "r"(a[2]), "r"(a[3]), "r"(b[0]), "r"(b[1]));
}

// ---------------------------------------------------------------------------
// Block-wide reduction of two floats across 256 threads (result on tid 0).
// ---------------------------------------------------------------------------
__device__ __forceinline__ void block_reduce2_256(float& a, float& b) {
    __shared__ float sa[8], sb[8];
    int lane = threadIdx.x & 31;
    int w = threadIdx.x >> 5;
#pragma unroll
    for (int o = 16; o > 0; o >>= 1) {
        a += __shfl_down_sync(0xffffffffu, a, o);
        b += __shfl_down_sync(0xffffffffu, b, o);
    }
    if (lane == 0) { sa[w] = a; sb[w] = b; }
    __syncthreads();
    if (w == 0) {
        a = (lane < 8) ? sa[lane] : 0.0f;
        b = (lane < 8) ? sb[lane] : 0.0f;
#pragma unroll
        for (int o = 4; o > 0; o >>= 1) {
            a += __shfl_down_sync(0xffu, a, o);
            b += __shfl_down_sync(0xffu, b, o);
        }
    }
}

__device__ __forceinline__ void split_store(float v, bf16* hi, bf16* lo, size_t i) {
    bf16 h = __float2bfloat16(v);
    hi[i] = h;
    lo[i] = __float2bfloat16(v - __bfloat162float(h));
}

// ---------------------------------------------------------------------------
// Kernel 1: layernorm(x) over C, fused fp32 -> bf16 hi/lo split.
// ---------------------------------------------------------------------------
__global__ __launch_bounds__(256) void k_ln_in(const float* __restrict__ x,
                                               const float* __restrict__ gam,
                                               const float* __restrict__ bet) {
    int t = blockIdx.x;
    int tid = threadIdx.x;
    const float* row = x + (size_t)t * CC;
    float v0 = row[tid], v1 = row[tid + 256], v2 = row[tid + 512];
    float s = v0 + v1 + v2;
    float sq = v0 * v0 + v1 * v1 + v2 * v2;
    block_reduce2_256(s, sq);
    __shared__ float s_mu, s_rstd;
    if (tid == 0) {
        float mu = s * (1.0f / CC);
        float var = sq * (1.0f / CC) - mu * mu;
        s_mu = mu;
        s_rstd = rsqrtf(var + 1e-5f);
    }
    __syncthreads();
    float mu = s_mu, rstd = s_rstd;
    size_t base = (size_t)t * CC;
    split_store((v0 - mu) * rstd * gam[tid] + bet[tid], g_ahi, g_alo, base + tid);
    split_store((v1 - mu) * rstd * gam[tid + 256] + bet[tid + 256], g_ahi, g_alo, base + tid + 256);
    split_store((v2 - mu) * rstd * gam[tid + 512] + bet[tid + 512], g_ahi, g_alo, base + tid + 512);
}

// ---------------------------------------------------------------------------
// Weight prep: w[K,N] fp32 -> hi/lo bf16 transposed [N,K].
// ---------------------------------------------------------------------------
__global__ __launch_bounds__(256) void k_wprep(const float* __restrict__ w,
                                               int N, int which) {
    __shared__ float t[32][33];
    bf16* bhi = which ? g_bphi : g_bqhi;
    bf16* blo = which ? g_bplo : g_bqlo;
    const int K = CC;
    int n0 = blockIdx.x * 32, k0 = blockIdx.y * 32;
    int tx = threadIdx.x & 31, ty = threadIdx.x >> 5;
    for (int i = ty; i < 32; i += 8) t[i][tx] = w[(size_t)(k0 + i) * N + n0 + tx];
    __syncthreads();
    for (int i = ty; i < 32; i += 8) {
        float v = t[tx][i];  // element (k0+tx, n0+i)
        size_t o = (size_t)(n0 + i) * K + k0 + tx;
        bf16 h = __float2bfloat16(v);
        bhi[o] = h;
        blo[o] = __float2bfloat16(v - __bfloat162float(h));
    }
}

// ---------------------------------------------------------------------------
// mma.sync bf16 GEMM with 3-term hi/lo compensation.
// C[M,NT] = A[M,768] @ B^T   (A = g_ahi/g_alo, B[n,k] hi/lo)
// CTA 128x128, BK=32, 3-stage cp.async. 8 warps: 2(M) x 4(N), warp tile 64x32.
// Smem rows padded to 40 bf16 (80B) -> conflict-free ldmatrix.
// ---------------------------------------------------------------------------
#define GBM 128
#define GBN 128
#define GBK 32
#define PADK 40
#define TILE_B (128 * PADK * 2)       // 10240 bytes per 128x32 tile
#define STAGE_B (4 * TILE_B)          // Ahi, Alo, Bhi, Blo
#define NSTG 3
#define GSMEM (NSTG * STAGE_B)        // 122880 bytes

__device__ __forceinline__ void load_tile(uint32_t dst, const bf16* __restrict__ g,
                                          int row0, int kc, int tid) {
#pragma unroll
    for (int i = 0; i < 2; i++) {
        int idx = tid + i * 256;
        int r = idx >> 2, seg = idx & 3;
        cpa16(dst + (uint32_t)(r * PADK + seg * 8) * 2,
              g + (size_t)(row0 + r) * CC + kc + seg * 8);
    }
}

template <int LDC_>
__global__ __launch_bounds__(256, 1) void k_gemm(const bf16* __restrict__ Bhi,
                                                 const bf16* __restrict__ Blo,
                                                 float* __restrict__ C) {
    extern __shared__ char dsm[];
    uint32_t sb = smem_u32(dsm);
    int tid = threadIdx.x, lane = tid & 31, wid = tid >> 5;
    int wm = wid >> 2, wn = wid & 3;               // warp grid 2 x 4
    int bm = blockIdx.y * GBM, bn = blockIdx.x * GBN;
    const int kt = CC / GBK;                       // 24 chunks

    // ldmatrix per-thread row/col offsets
    uint32_t a_row = (uint32_t)(wm * 64 + (lane & 15));
    uint32_t a_ko = (uint32_t)((lane >> 4) * 8);
    uint32_t b_row = (uint32_t)(wn * 32 + (lane & 7) + ((lane >> 4) << 3));
    uint32_t b_ko = (uint32_t)(((lane >> 3) & 1) * 8);

    float acc[4][4][4];
#pragma unroll
    for (int i = 0; i < 4; i++)
#pragma unroll
        for (int j = 0; j < 4; j++)
#pragma unroll
            for (int r = 0; r < 4; r++) acc[i][j][r] = 0.0f;

    // prologue: stages 0,1
#pragma unroll
    for (int c = 0; c < 2; c++) {
        uint32_t st = sb + c * STAGE_B;
        int kc = c * GBK;
        load_tile(st,              g_ahi, bm, kc, tid);
        load_tile(st + TILE_B,     g_alo, bm, kc, tid);
        load_tile(st + 2 * TILE_B, Bhi,   bn, kc, tid);
        load_tile(st + 3 * TILE_B, Blo,   bn, kc, tid);
        asm volatile("cp.async.commit_group;" ::: "memory");
    }

    for (int c = 0; c < kt; c++) {
        bool more = (c + 2 < kt);
        if (more)
            asm volatile("cp.async.wait_group 1;" ::: "memory");
        else
            asm volatile("cp.async.wait_group 0;" ::: "memory");
        __syncthreads();

        if (more) {
            uint32_t st = sb + ((c + 2) % NSTG) * STAGE_B;
            int kc = (c + 2) * GBK;
            load_tile(st,              g_ahi, bm, kc, tid);
            load_tile(st + TILE_B,     g_alo, bm, kc, tid);
            load_tile(st + 2 * TILE_B, Bhi,   bn, kc, tid);
            load_tile(st + 3 * TILE_B, Blo,   bn, kc, tid);
            asm volatile("cp.async.commit_group;" ::: "memory");
        }

        uint32_t st = sb + (c % NSTG) * STAGE_B;
#pragma unroll
        for (int ks = 0; ks < 2; ks++) {
            uint32_t ahi_f[4][4], alo_f[4][4];
            uint32_t bhi_f[4][2], blo_f[4][2];
#pragma unroll
            for (int mt = 0; mt < 4; mt++) {
                uint32_t off = ((a_row + mt * 16) * PADK + ks * 16 + a_ko) * 2;
                ldsm4(ahi_f[mt], st + off);
                ldsm4(alo_f[mt], st + TILE_B + off);
            }
#pragma unroll
            for (int p = 0; p < 2; p++) {
                uint32_t off = ((b_row + p * 16) * PADK + ks * 16 + b_ko) * 2;
                uint32_t r[4];
                ldsm4(r, st + 2 * TILE_B + off);
                bhi_f[2 * p][0] = r[0]; bhi_f[2 * p][1] = r[1];
                bhi_f[2 * p + 1][0] = r[2]; bhi_f[2 * p + 1][1] = r[3];
                ldsm4(r, st + 3 * TILE_B + off);
                blo_f[2 * p][0] = r[0]; blo_f[2 * p][1] = r[1];
                blo_f[2 * p + 1][0] = r[2]; blo_f[2 * p + 1][1] = r[3];
            }
#pragma unroll
            for (int mt = 0; mt < 4; mt++)
#pragma unroll
                for (int nt = 0; nt < 4; nt++) {
                    mma_bf16(acc[mt][nt], ahi_f[mt], bhi_f[nt]);
                    mma_bf16(acc[mt][nt], ahi_f[mt], blo_f[nt]);
                    mma_bf16(acc[mt][nt], alo_f[mt], bhi_f[nt]);
                }
        }
    }

    // epilogue
#pragma unroll
    for (int mt = 0; mt < 4; mt++) {
        int r0 = bm + wm * 64 + mt * 16 + (lane >> 2);
#pragma unroll
        for (int nt = 0; nt < 4; nt++) {
            int cidx = bn + wn * 32 + nt * 8 + (lane & 3) * 2;
            float* p0 = C + (size_t)r0 * LDC_ + cidx;
            float* p1 = C + (size_t)(r0 + 8) * LDC_ + cidx;
            *(float2*)p0 = make_float2(acc[mt][nt][0], acc[mt][nt][1]);
            *(float2*)p1 = make_float2(acc[mt][nt][2], acc[mt][nt][3]);
        }
    }
}

// ---------------------------------------------------------------------------
// per-token inverse L2 norms of q and k.
// ---------------------------------------------------------------------------
__global__ __launch_bounds__(256) void k_norms() {
    int t = blockIdx.x;
    int tid = threadIdx.x;
    const float* qrow = g_qkv + (size_t)t * QKVD;
    const float* krow = qrow + EE;
    float q0 = qrow[tid], q1 = qrow[tid + 256], q2 = qrow[tid + 512];
    float k0 = krow[tid], k1 = krow[tid + 256], k2 = krow[tid + 512];
    float sq = q0 * q0 + q1 * q1 + q2 * q2;
    float sk = k0 * k0 + k1 * k1 + k2 * k2;
    block_reduce2_256(sq, sk);
    if (tid == 0) {
        g_qinv[t] = 1.0f / fmaxf(sqrtf(sq), 1e-12f);
        g_kinv[t] = 1.0f / fmaxf(sqrtf(sk), 1e-12f);
    }
}

// ---------------------------------------------------------------------------
// kv partial sums: kv[b,e] = sum_t phi_k[t,e] * v[t,e]
// ---------------------------------------------------------------------------
__global__ __launch_bounds__(256) void k_kvred() {
    int b = blockIdx.y;
    int chunk = blockIdx.x;
    int tid = threadIdx.x;
    float a0 = 0.f, a1 = 0.f, a2 = 0.f;
    int t0 = b * NN + chunk * 128;
    for (int i = 0; i < 128; i++) {
        const float* row = g_qkv + (size_t)(t0 + i) * QKVD;
        const float* kr = row + EE;
        const float* vr = row + 2 * EE;
        float ki = g_kinv[t0 + i];
        a0 += (kr[tid] * ki) * vr[tid];
        a1 += (kr[tid + 256] * ki) * vr[tid + 256];
        a2 += (kr[tid + 512] * ki) * vr[tid + 512];
    }
    float* dst = g_kvpart + ((size_t)chunk * BQ + b) * EE;
    dst[tid] = a0; dst[tid + 256] = a1; dst[tid + 512] = a2;
}

__global__ __launch_bounds__(256) void k_kvsum() {
    int i = blockIdx.x * 256 + threadIdx.x;
    float s = 0.f;
#pragma unroll
    for (int c = 0; c < 32; c++) s += g_kvpart[(size_t)c * BQ * EE + i];
    g_kv[i] = s;
}

// ---------------------------------------------------------------------------
// attn = phi_q * kv[b]; layernorm over E; fused bf16 hi/lo split.
// ---------------------------------------------------------------------------
__global__ __launch_bounds__(256) void k_attn_ln(const float* __restrict__ gam,
                                                 const float* __restrict__ bet) {
    int t = blockIdx.x;
    int b = t >> 12;
    int tid = threadIdx.x;
    const float* qrow = g_qkv + (size_t)t * QKVD;
    const float* kvb = g_kv + b * EE;
    float qi = g_qinv[t];
    float a0 = (qrow[tid] * qi) * kvb[tid];
    float a1 = (qrow[tid + 256] * qi) * kvb[tid + 256];
    float a2 = (qrow[tid + 512] * qi) * kvb[tid + 512];
    float s = a0 + a1 + a2;
    float sq = a0 * a0 + a1 * a1 + a2 * a2;
    block_reduce2_256(s, sq);
    __shared__ float s_mu, s_rstd;
    if (tid == 0) {
        float mu = s * (1.0f / EE);
        float var = sq * (1.0f / EE) - mu * mu;
        s_mu = mu;
        s_rstd = rsqrtf(var + 1e-5f);
    }
    __syncthreads();
    float mu = s_mu, rstd = s_rstd;
    size_t base = (size_t)t * EE;
    split_store((a0 - mu) * rstd * gam[tid] + bet[tid], g_ahi, g_alo, base + tid);
    split_store((a1 - mu) * rstd * gam[tid + 256] + bet[tid + 256], g_ahi, g_alo, base + tid + 256);
    split_store((a2 - mu) * rstd * gam[tid + 512] + bet[tid + 512], g_ahi, g_alo, base + tid + 512);
}

// ---------------------------------------------------------------------------
extern "C" void kernel_launch(void* const* d_in, const int* in_sizes, int n_in,
                              void* d_out, int out_size) {
    const float* x        = (const float*)d_in[0];
    const float* w_qkv    = (const float*)d_in[1];
    const float* w_proj   = (const float*)d_in[2];
    const float* ln_in_g  = (const float*)d_in[3];
    const float* ln_in_b  = (const float*)d_in[4];
    const float* ln_out_g = (const float*)d_in[5];
    const float* ln_out_b = (const float*)d_in[6];
    float* out = (float*)d_out;

    cudaFuncSetAttribute(k_gemm<QKVD>, cudaFuncAttributeMaxDynamicSharedMemorySize, GSMEM);
    cudaFuncSetAttribute(k_gemm<CC>, cudaFuncAttributeMaxDynamicSharedMemorySize, GSMEM);

    bf16* bqhi; cudaGetSymbolAddress((void**)&bqhi, g_bqhi);
    bf16* bqlo; cudaGetSymbolAddress((void**)&bqlo, g_bqlo);
    bf16* bphi; cudaGetSymbolAddress((void**)&bphi, g_bphi);
    bf16* bplo; cudaGetSymbolAddress((void**)&bplo, g_bplo);
    float* qkv; cudaGetSymbolAddress((void**)&qkv, g_qkv);

    k_ln_in<<<MM, 256>>>(x, ln_in_g, ln_in_b);
    k_wprep<<<dim3(QKVD / 32, CC / 32), 256>>>(w_qkv, QKVD, 0);
    k_wprep<<<dim3(CC / 32, CC / 32), 256>>>(w_proj, CC, 1);
    k_gemm<QKVD><<<dim3(QKVD / GBN, MM / GBM), 256, GSMEM>>>(bqhi, bqlo, qkv);
    k_norms<<<MM, 256>>>();
    k_kvred<<<dim3(32, BQ), 256>>>();
    k_kvsum<<<BQ * EE / 256, 256>>>();
    k_attn_ln<<<MM, 256>>>(ln_out_g, ln_out_b);
    k_gemm<CC><<<dim3(CC / GBN, MM / GBM), 256, GSMEM>>>(bphi, bplo, out);
}

// round 7
// speedup vs baseline: 2.1377x; 1.1912x over previous
#include <cuda_runtime.h>
#include <cuda_bf16.h>
#include <cstdint>

// Problem constants
#define BQ 8
#define NN 4096
#define CC 768
#define EE 768
#define MM (BQ * NN)     // 32768 tokens
#define QKVD (3 * EE)    // 2304

using bf16 = __nv_bfloat16;

// ---------------- device scratch (no allocation allowed) -------------------
__device__ __align__(128) float g_qkv[(size_t)MM * QKVD];   // GEMM1 out (fp32)
__device__ __align__(128) bf16  g_ahi[(size_t)MM * CC];     // A hi
__device__ __align__(128) bf16  g_alo[(size_t)MM * CC];     // A lo
__device__ __align__(128) bf16  g_bqhi[(size_t)QKVD * CC];  // w_qkv^T hi [2304,768]
__device__ __align__(128) bf16  g_bqlo[(size_t)QKVD * CC];
__device__ __align__(128) bf16  g_bphi[(size_t)EE * CC];    // w_proj^T hi [768,768]
__device__ __align__(128) bf16  g_bplo[(size_t)EE * CC];
__device__ float g_kvpart[32 * BQ * EE];
__device__ float g_kv[BQ * EE];
__device__ float g_qinv[MM];
__device__ float g_kinv[MM];

// ---------------------------- helpers --------------------------------------
__device__ __forceinline__ uint32_t smem_u32(const void* p) {
    uint32_t a;
    asm("{ .reg .u64 t; cvta.to.shared.u64 t, %1; cvt.u32.u64 %0, t; }"
        : "=r"(a) : "l"(p));
    return a;
}
__device__ __forceinline__ void cpa16(uint32_t dst, const void* src) {
    asm volatile("cp.async.cg.shared.global [%0], [%1], 16;" :: "r"(dst), "l"(src));
}
__device__ __forceinline__ void ldsm4(uint32_t* r, uint32_t addr) {
    asm volatile("ldmatrix.sync.aligned.m8n8.x4.shared.b16 {%0,%1,%2,%3}, [%4];"
                 : "=r"(r[0]), "=r"(r[1]), "=r"(r[2]), "=r"(r[3]) : "r"(addr));
}
__device__ __forceinline__ void mma_bf16(float* d, const uint32_t* a,
                                         const uint32_t* b) {
    asm volatile(
        "mma.sync.aligned.m16n8k16.row.col.f32.bf16.bf16.f32 "
        "{%0,%1,%2,%3},{%4,%5,%6,%7},{%8,%9},{%0,%1,%2,%3};"
        : "+f"(d[0]), "+f"(d[1]), "+f"(d[2]), "+f"(d[3])
        : "r"(a[0]), "r"(a[1]), "r"(a[2]), "r"(a[3]), "r"(b[0]), "r"(b[1]));
}

// ---------------------------------------------------------------------------
// Block-wide reduction of two floats across 256 threads (result on tid 0).
// ---------------------------------------------------------------------------
__device__ __forceinline__ void block_reduce2_256(float& a, float& b) {
    __shared__ float sa[8], sb[8];
    int lane = threadIdx.x & 31;
    int w = threadIdx.x >> 5;
#pragma unroll
    for (int o = 16; o > 0; o >>= 1) {
        a += __shfl_down_sync(0xffffffffu, a, o);
        b += __shfl_down_sync(0xffffffffu, b, o);
    }
    if (lane == 0) { sa[w] = a; sb[w] = b; }
    __syncthreads();
    if (w == 0) {
        a = (lane < 8) ? sa[lane] : 0.0f;
        b = (lane < 8) ? sb[lane] : 0.0f;
#pragma unroll
        for (int o = 4; o > 0; o >>= 1) {
            a += __shfl_down_sync(0xffu, a, o);
            b += __shfl_down_sync(0xffu, b, o);
        }
    }
}

__device__ __forceinline__ void split_store(float v, bf16* hi, bf16* lo, size_t i) {
    bf16 h = __float2bfloat16(v);
    hi[i] = h;
    lo[i] = __float2bfloat16(v - __bfloat162float(h));
}

// ---------------------------------------------------------------------------
// Kernel 1: layernorm(x) over C, fused fp32 -> bf16 hi/lo split.
// ---------------------------------------------------------------------------
__global__ __launch_bounds__(256) void k_ln_in(const float* __restrict__ x,
                                               const float* __restrict__ gam,
                                               const float* __restrict__ bet) {
    int t = blockIdx.x;
    int tid = threadIdx.x;
    const float* row = x + (size_t)t * CC;
    float v0 = row[tid], v1 = row[tid + 256], v2 = row[tid + 512];
    float s = v0 + v1 + v2;
    float sq = v0 * v0 + v1 * v1 + v2 * v2;
    block_reduce2_256(s, sq);
    __shared__ float s_mu, s_rstd;
    if (tid == 0) {
        float mu = s * (1.0f / CC);
        float var = sq * (1.0f / CC) - mu * mu;
        s_mu = mu;
        s_rstd = rsqrtf(var + 1e-5f);
    }
    __syncthreads();
    float mu = s_mu, rstd = s_rstd;
    size_t base = (size_t)t * CC;
    split_store((v0 - mu) * rstd * gam[tid] + bet[tid], g_ahi, g_alo, base + tid);
    split_store((v1 - mu) * rstd * gam[tid + 256] + bet[tid + 256], g_ahi, g_alo, base + tid + 256);
    split_store((v2 - mu) * rstd * gam[tid + 512] + bet[tid + 512], g_ahi, g_alo, base + tid + 512);
}

// ---------------------------------------------------------------------------
// Weight prep: w[K,N] fp32 -> hi/lo bf16 transposed [N,K].
// ---------------------------------------------------------------------------
__global__ __launch_bounds__(256) void k_wprep(const float* __restrict__ w,
                                               int N, int which) {
    __shared__ float t[32][33];
    bf16* bhi = which ? g_bphi : g_bqhi;
    bf16* blo = which ? g_bplo : g_bqlo;
    const int K = CC;
    int n0 = blockIdx.x * 32, k0 = blockIdx.y * 32;
    int tx = threadIdx.x & 31, ty = threadIdx.x >> 5;
    for (int i = ty; i < 32; i += 8) t[i][tx] = w[(size_t)(k0 + i) * N + n0 + tx];
    __syncthreads();
    for (int i = ty; i < 32; i += 8) {
        float v = t[tx][i];  // element (k0+tx, n0+i)
        size_t o = (size_t)(n0 + i) * K + k0 + tx;
        bf16 h = __float2bfloat16(v);
        bhi[o] = h;
        blo[o] = __float2bfloat16(v - __bfloat162float(h));
    }
}

// ---------------------------------------------------------------------------
// mma.sync bf16 GEMM with 3-term hi/lo compensation.
// C[M,NT] = A[M,768] @ B^T   (A = g_ahi/g_alo, B[n,k] hi/lo)
// CTA 128x128, BK=32, 2-stage cp.async, 2 CTAs/SM. 8 warps: 2(M) x 4(N),
// warp tile 64x32. Smem rows padded to 40 bf16 (80B) -> conflict-free ldmatrix.
// ---------------------------------------------------------------------------
#define GBM 128
#define GBN 128
#define GBK 32
#define PADK 40
#define TILE_B (128 * PADK * 2)       // 10240 bytes per 128x32 tile
#define STAGE_B (4 * TILE_B)          // Ahi, Alo, Bhi, Blo
#define NSTG 2
#define GSMEM (NSTG * STAGE_B)        // 81920 bytes -> 2 CTAs/SM

__device__ __forceinline__ void load_tile(uint32_t dst, const bf16* __restrict__ g,
                                          int row0, int kc, int tid) {
#pragma unroll
    for (int i = 0; i < 2; i++) {
        int idx = tid + i * 256;
        int r = idx >> 2, seg = idx & 3;
        cpa16(dst + (uint32_t)(r * PADK + seg * 8) * 2,
              g + (size_t)(row0 + r) * CC + kc + seg * 8);
    }
}

template <int LDC_>
__global__ __launch_bounds__(256, 2) void k_gemm(const bf16* __restrict__ Bhi,
                                                 const bf16* __restrict__ Blo,
                                                 float* __restrict__ C) {
    extern __shared__ char dsm[];
    uint32_t sb = smem_u32(dsm);
    int tid = threadIdx.x, lane = tid & 31, wid = tid >> 5;
    int wm = wid >> 2, wn = wid & 3;               // warp grid 2 x 4
    int bm = blockIdx.y * GBM, bn = blockIdx.x * GBN;
    const int kt = CC / GBK;                       // 24 chunks

    // ldmatrix per-thread row/col offsets
    uint32_t a_row = (uint32_t)(wm * 64 + (lane & 15));
    uint32_t a_ko = (uint32_t)((lane >> 4) * 8);
    uint32_t b_row = (uint32_t)(wn * 32 + (lane & 7) + ((lane >> 4) << 3));
    uint32_t b_ko = (uint32_t)(((lane >> 3) & 1) * 8);

    float acc[4][4][4];
#pragma unroll
    for (int i = 0; i < 4; i++)
#pragma unroll
        for (int j = 0; j < 4; j++)
#pragma unroll
            for (int r = 0; r < 4; r++) acc[i][j][r] = 0.0f;

    // prologue: chunks 0,1 into stages 0,1
#pragma unroll
    for (int c = 0; c < 2; c++) {
        uint32_t st = sb + c * STAGE_B;
        int kc = c * GBK;
        load_tile(st,              g_ahi, bm, kc, tid);
        load_tile(st + TILE_B,     g_alo, bm, kc, tid);
        load_tile(st + 2 * TILE_B, Bhi,   bn, kc, tid);
        load_tile(st + 3 * TILE_B, Blo,   bn, kc, tid);
        asm volatile("cp.async.commit_group;" ::: "memory");
    }

    for (int c = 0; c < kt; c++) {
        bool more = (c + 2 < kt);
        if (more)
            asm volatile("cp.async.wait_group 1;" ::: "memory");
        else
            asm volatile("cp.async.wait_group 0;" ::: "memory");
        __syncthreads();

        uint32_t st = sb + (c & 1) * STAGE_B;
#pragma unroll
        for (int ks = 0; ks < 2; ks++) {
            uint32_t bhi_f[4][2], blo_f[4][2];
#pragma unroll
            for (int p = 0; p < 2; p++) {
                uint32_t off = ((b_row + p * 16) * PADK + ks * 16 + b_ko) * 2;
                uint32_t r[4];
                ldsm4(r, st + 2 * TILE_B + off);
                bhi_f[2 * p][0] = r[0]; bhi_f[2 * p][1] = r[1];
                bhi_f[2 * p + 1][0] = r[2]; bhi_f[2 * p + 1][1] = r[3];
                ldsm4(r, st + 3 * TILE_B + off);
                blo_f[2 * p][0] = r[0]; blo_f[2 * p][1] = r[1];
                blo_f[2 * p + 1][0] = r[2]; blo_f[2 * p + 1][1] = r[3];
            }
#pragma unroll
            for (int mt = 0; mt < 4; mt++) {
                uint32_t ahi_f[4], alo_f[4];
                uint32_t off = ((a_row + mt * 16) * PADK + ks * 16 + a_ko) * 2;
                ldsm4(ahi_f, st + off);
                ldsm4(alo_f, st + TILE_B + off);
#pragma unroll
                for (int nt = 0; nt < 4; nt++) {
                    mma_bf16(acc[mt][nt], ahi_f, bhi_f[nt]);
                    mma_bf16(acc[mt][nt], ahi_f, blo_f[nt]);
                    mma_bf16(acc[mt][nt], alo_f, bhi_f[nt]);
                }
            }
        }
        __syncthreads();   // all warps done reading stage (c&1) before reload

        if (more) {
            uint32_t st2 = sb + ((c + 2) & 1) * STAGE_B;
            int kc = (c + 2) * GBK;
            load_tile(st2,              g_ahi, bm, kc, tid);
            load_tile(st2 + TILE_B,     g_alo, bm, kc, tid);
            load_tile(st2 + 2 * TILE_B, Bhi,   bn, kc, tid);
            load_tile(st2 + 3 * TILE_B, Blo,   bn, kc, tid);
            asm volatile("cp.async.commit_group;" ::: "memory");
        }
    }

    // epilogue
#pragma unroll
    for (int mt = 0; mt < 4; mt++) {
        int r0 = bm + wm * 64 + mt * 16 + (lane >> 2);
#pragma unroll
        for (int nt = 0; nt < 4; nt++) {
            int cidx = bn + wn * 32 + nt * 8 + (lane & 3) * 2;
            float* p0 = C + (size_t)r0 * LDC_ + cidx;
            float* p1 = C + (size_t)(r0 + 8) * LDC_ + cidx;
            *(float2*)p0 = make_float2(acc[mt][nt][0], acc[mt][nt][1]);
            *(float2*)p1 = make_float2(acc[mt][nt][2], acc[mt][nt][3]);
        }
    }
}

// ---------------------------------------------------------------------------
// per-token inverse L2 norms of q and k.
// ---------------------------------------------------------------------------
__global__ __launch_bounds__(256) void k_norms() {
    int t = blockIdx.x;
    int tid = threadIdx.x;
    const float* qrow = g_qkv + (size_t)t * QKVD;
    const float* krow = qrow + EE;
    float q0 = qrow[tid], q1 = qrow[tid + 256], q2 = qrow[tid + 512];
    float k0 = krow[tid], k1 = krow[tid + 256], k2 = krow[tid + 512];
    float sq = q0 * q0 + q1 * q1 + q2 * q2;
    float sk = k0 * k0 + k1 * k1 + k2 * k2;
    block_reduce2_256(sq, sk);
    if (tid == 0) {
        g_qinv[t] = 1.0f / fmaxf(sqrtf(sq), 1e-12f);
        g_kinv[t] = 1.0f / fmaxf(sqrtf(sk), 1e-12f);
    }
}

// ---------------------------------------------------------------------------
// kv partial sums: kv[b,e] = sum_t phi_k[t,e] * v[t,e]
// ---------------------------------------------------------------------------
__global__ __launch_bounds__(256) void k_kvred() {
    int b = blockIdx.y;
    int chunk = blockIdx.x;
    int tid = threadIdx.x;
    float a0 = 0.f, a1 = 0.f, a2 = 0.f;
    int t0 = b * NN + chunk * 128;
    for (int i = 0; i < 128; i++) {
        const float* row = g_qkv + (size_t)(t0 + i) * QKVD;
        const float* kr = row + EE;
        const float* vr = row + 2 * EE;
        float ki = g_kinv[t0 + i];
        a0 += (kr[tid] * ki) * vr[tid];
        a1 += (kr[tid + 256] * ki) * vr[tid + 256];
        a2 += (kr[tid + 512] * ki) * vr[tid + 512];
    }
    float* dst = g_kvpart + ((size_t)chunk * BQ + b) * EE;
    dst[tid] = a0; dst[tid + 256] = a1; dst[tid + 512] = a2;
}

__global__ __launch_bounds__(256) void k_kvsum() {
    int i = blockIdx.x * 256 + threadIdx.x;
    float s = 0.f;
#pragma unroll
    for (int c = 0; c < 32; c++) s += g_kvpart[(size_t)c * BQ * EE + i];
    g_kv[i] = s;
}

// ---------------------------------------------------------------------------
// attn = phi_q * kv[b]; layernorm over E; fused bf16 hi/lo split.
// ---------------------------------------------------------------------------
__global__ __launch_bounds__(256) void k_attn_ln(const float* __restrict__ gam,
                                                 const float* __restrict__ bet) {
    int t = blockIdx.x;
    int b = t >> 12;
    int tid = threadIdx.x;
    const float* qrow = g_qkv + (size_t)t * QKVD;
    const float* kvb = g_kv + b * EE;
    float qi = g_qinv[t];
    float a0 = (qrow[tid] * qi) * kvb[tid];
    float a1 = (qrow[tid + 256] * qi) * kvb[tid + 256];
    float a2 = (qrow[tid + 512] * qi) * kvb[tid + 512];
    float s = a0 + a1 + a2;
    float sq = a0 * a0 + a1 * a1 + a2 * a2;
    block_reduce2_256(s, sq);
    __shared__ float s_mu, s_rstd;
    if (tid == 0) {
        float mu = s * (1.0f / EE);
        float var = sq * (1.0f / EE) - mu * mu;
        s_mu = mu;
        s_rstd = rsqrtf(var + 1e-5f);
    }
    __syncthreads();
    float mu = s_mu, rstd = s_rstd;
    size_t base = (size_t)t * EE;
    split_store((a0 - mu) * rstd * gam[tid] + bet[tid], g_ahi, g_alo, base + tid);
    split_store((a1 - mu) * rstd * gam[tid + 256] + bet[tid + 256], g_ahi, g_alo, base + tid + 256);
    split_store((a2 - mu) * rstd * gam[tid + 512] + bet[tid + 512], g_ahi, g_alo, base + tid + 512);
}

// ---------------------------------------------------------------------------
extern "C" void kernel_launch(void* const* d_in, const int* in_sizes, int n_in,
                              void* d_out, int out_size) {
    const float* x        = (const float*)d_in[0];
    const float* w_qkv    = (const float*)d_in[1];
    const float* w_proj   = (const float*)d_in[2];
    const float* ln_in_g  = (const float*)d_in[3];
    const float* ln_in_b  = (const float*)d_in[4];
    const float* ln_out_g = (const float*)d_in[5];
    const float* ln_out_b = (const float*)d_in[6];
    float* out = (float*)d_out;

    cudaFuncSetAttribute(k_gemm<QKVD>, cudaFuncAttributeMaxDynamicSharedMemorySize, GSMEM);
    cudaFuncSetAttribute(k_gemm<CC>, cudaFuncAttributeMaxDynamicSharedMemorySize, GSMEM);

    bf16* bqhi; cudaGetSymbolAddress((void**)&bqhi, g_bqhi);
    bf16* bqlo; cudaGetSymbolAddress((void**)&bqlo, g_bqlo);
    bf16* bphi; cudaGetSymbolAddress((void**)&bphi, g_bphi);
    bf16* bplo; cudaGetSymbolAddress((void**)&bplo, g_bplo);
    float* qkv; cudaGetSymbolAddress((void**)&qkv, g_qkv);

    k_ln_in<<<MM, 256>>>(x, ln_in_g, ln_in_b);
    k_wprep<<<dim3(QKVD / 32, CC / 32), 256>>>(w_qkv, QKVD, 0);
    k_wprep<<<dim3(CC / 32, CC / 32), 256>>>(w_proj, CC, 1);
    k_gemm<QKVD><<<dim3(QKVD / GBN, MM / GBM), 256, GSMEM>>>(bqhi, bqlo, qkv);
    k_norms<<<MM, 256>>>();
    k_kvred<<<dim3(32, BQ), 256>>>();
    k_kvsum<<<BQ * EE / 256, 256>>>();
    k_attn_ln<<<MM, 256>>>(ln_out_g, ln_out_b);
    k_gemm<CC><<<dim3(CC / GBN, MM / GBM), 256, GSMEM>>>(bphi, bplo, out);
}

// round 8
// speedup vs baseline: 2.1378x; 1.0000x over previous
#include <cuda_runtime.h>
#include <cuda_bf16.h>
#include <cstdint>

// Problem constants
#define BQ 8
#define NN 4096
#define CC 768
#define EE 768
#define MM (BQ * NN)     // 32768 tokens
#define QKVD (3 * EE)    // 2304

using bf16 = __nv_bfloat16;

// ---------------- device scratch (no allocation allowed) -------------------
__device__ __align__(128) float g_qkv[(size_t)MM * QKVD];   // GEMM1 out (fp32)
__device__ __align__(128) bf16  g_ahi[(size_t)MM * CC];     // A hi
__device__ __align__(128) bf16  g_alo[(size_t)MM * CC];     // A lo
__device__ __align__(128) bf16  g_bqhi[(size_t)QKVD * CC];  // w_qkv^T hi [2304,768]
__device__ __align__(128) bf16  g_bqlo[(size_t)QKVD * CC];
__device__ __align__(128) bf16  g_bphi[(size_t)EE * CC];    // w_proj^T hi [768,768]
__device__ __align__(128) bf16  g_bplo[(size_t)EE * CC];
__device__ float g_kvpart[32 * BQ * EE];
__device__ float g_kv[BQ * EE];
__device__ float g_kinv[MM];

// ---------------------------- helpers --------------------------------------
__device__ __forceinline__ uint32_t smem_u32(const void* p) {
    uint32_t a;
    asm("{ .reg .u64 t; cvta.to.shared.u64 t, %1; cvt.u32.u64 %0, t; }"
        : "=r"(a) : "l"(p));
    return a;
}
__device__ __forceinline__ void cpa16(uint32_t dst, const void* src) {
    asm volatile("cp.async.cg.shared.global [%0], [%1], 16;" :: "r"(dst), "l"(src));
}
__device__ __forceinline__ void ldsm4(uint32_t* r, uint32_t addr) {
    asm volatile("ldmatrix.sync.aligned.m8n8.x4.shared.b16 {%0,%1,%2,%3}, [%4];"
                 : "=r"(r[0]), "=r"(r[1]), "=r"(r[2]), "=r"(r[3]) : "r"(addr));
}
__device__ __forceinline__ void mma_bf16(float* d, const uint32_t* a,
                                         const uint32_t* b) {
    asm volatile(
        "mma.sync.aligned.m16n8k16.row.col.f32.bf16.bf16.f32 "
        "{%0,%1,%2,%3},{%4,%5,%6,%7},{%8,%9},{%0,%1,%2,%3};"
        : "+f"(d[0]), "+f"(d[1]), "+f"(d[2]), "+f"(d[3])
        : "r"(a[0]), "r"(a[1]), "r"(a[2]), "r"(a[3]), "r"(b[0]), "r"(b[1]));
}

// ---------------------------------------------------------------------------
// Block-wide reduction of two floats across 256 threads (result on tid 0).
// ---------------------------------------------------------------------------
__device__ __forceinline__ void block_reduce2_256(float& a, float& b) {
    __shared__ float sa[8], sb[8];
    int lane = threadIdx.x & 31;
    int w = threadIdx.x >> 5;
#pragma unroll
    for (int o = 16; o > 0; o >>= 1) {
        a += __shfl_down_sync(0xffffffffu, a, o);
        b += __shfl_down_sync(0xffffffffu, b, o);
    }
    if (lane == 0) { sa[w] = a; sb[w] = b; }
    __syncthreads();
    if (w == 0) {
        a = (lane < 8) ? sa[lane] : 0.0f;
        b = (lane < 8) ? sb[lane] : 0.0f;
#pragma unroll
        for (int o = 4; o > 0; o >>= 1) {
            a += __shfl_down_sync(0xffu, a, o);
            b += __shfl_down_sync(0xffu, b, o);
        }
    }
}

__device__ __forceinline__ void split_store(float v, bf16* hi, bf16* lo, size_t i) {
    bf16 h = __float2bfloat16(v);
    hi[i] = h;
    lo[i] = __float2bfloat16(v - __bfloat162float(h));
}

// ---------------------------------------------------------------------------
// Kernel 1: layernorm(x) over C, fused fp32 -> bf16 hi/lo split.
// ---------------------------------------------------------------------------
__global__ __launch_bounds__(256) void k_ln_in(const float* __restrict__ x,
                                               const float* __restrict__ gam,
                                               const float* __restrict__ bet) {
    int t = blockIdx.x;
    int tid = threadIdx.x;
    const float* row = x + (size_t)t * CC;
    float v0 = row[tid], v1 = row[tid + 256], v2 = row[tid + 512];
    float s = v0 + v1 + v2;
    float sq = v0 * v0 + v1 * v1 + v2 * v2;
    block_reduce2_256(s, sq);
    __shared__ float s_mu, s_rstd;
    if (tid == 0) {
        float mu = s * (1.0f / CC);
        float var = sq * (1.0f / CC) - mu * mu;
        s_mu = mu;
        s_rstd = rsqrtf(var + 1e-5f);
    }
    __syncthreads();
    float mu = s_mu, rstd = s_rstd;
    size_t base = (size_t)t * CC;
    split_store((v0 - mu) * rstd * gam[tid] + bet[tid], g_ahi, g_alo, base + tid);
    split_store((v1 - mu) * rstd * gam[tid + 256] + bet[tid + 256], g_ahi, g_alo, base + tid + 256);
    split_store((v2 - mu) * rstd * gam[tid + 512] + bet[tid + 512], g_ahi, g_alo, base + tid + 512);
}

// ---------------------------------------------------------------------------
// Weight prep: w[K,N] fp32 -> hi/lo bf16 transposed [N,K].
// ---------------------------------------------------------------------------
__global__ __launch_bounds__(256) void k_wprep(const float* __restrict__ w,
                                               int N, int which) {
    __shared__ float t[32][33];
    bf16* bhi = which ? g_bphi : g_bqhi;
    bf16* blo = which ? g_bplo : g_bqlo;
    const int K = CC;
    int n0 = blockIdx.x * 32, k0 = blockIdx.y * 32;
    int tx = threadIdx.x & 31, ty = threadIdx.x >> 5;
    for (int i = ty; i < 32; i += 8) t[i][tx] = w[(size_t)(k0 + i) * N + n0 + tx];
    __syncthreads();
    for (int i = ty; i < 32; i += 8) {
        float v = t[tx][i];  // element (k0+tx, n0+i)
        size_t o = (size_t)(n0 + i) * K + k0 + tx;
        bf16 h = __float2bfloat16(v);
        bhi[o] = h;
        blo[o] = __float2bfloat16(v - __bfloat162float(h));
    }
}

// ---------------------------------------------------------------------------
// mma.sync bf16 GEMM with 3-term hi/lo compensation (term-major ILP order).
// C[M,NT] = A[M,768] @ B^T   (A = g_ahi/g_alo, B[n,k] hi/lo)
// CTA 128x128, BK=32, 2-stage cp.async, 2 CTAs/SM. 8 warps: 2(M) x 4(N),
// warp tile 64x32. Smem rows padded to 40 bf16 (80B) -> conflict-free ldmatrix.
// ---------------------------------------------------------------------------
#define GBM 128
#define GBN 128
#define GBK 32
#define PADK 40
#define TILE_B (128 * PADK * 2)       // 10240 bytes per 128x32 tile
#define STAGE_B (4 * TILE_B)          // Ahi, Alo, Bhi, Blo
#define NSTG 2
#define GSMEM (NSTG * STAGE_B)        // 81920 bytes -> 2 CTAs/SM

__device__ __forceinline__ void load_tile(uint32_t dst, const bf16* __restrict__ g,
                                          int row0, int kc, int tid) {
#pragma unroll
    for (int i = 0; i < 2; i++) {
        int idx = tid + i * 256;
        int r = idx >> 2, seg = idx & 3;
        cpa16(dst + (uint32_t)(r * PADK + seg * 8) * 2,
              g + (size_t)(row0 + r) * CC + kc + seg * 8);
    }
}

template <int LDC_>
__global__ __launch_bounds__(256, 2) void k_gemm(const bf16* __restrict__ Bhi,
                                                 const bf16* __restrict__ Blo,
                                                 float* __restrict__ C) {
    extern __shared__ char dsm[];
    uint32_t sb = smem_u32(dsm);
    int tid = threadIdx.x, lane = tid & 31, wid = tid >> 5;
    int wm = wid >> 2, wn = wid & 3;               // warp grid 2 x 4
    int bm = blockIdx.y * GBM, bn = blockIdx.x * GBN;
    const int kt = CC / GBK;                       // 24 chunks

    // ldmatrix per-thread row/col offsets
    uint32_t a_row = (uint32_t)(wm * 64 + (lane & 15));
    uint32_t a_ko = (uint32_t)((lane >> 4) * 8);
    uint32_t b_row = (uint32_t)(wn * 32 + (lane & 7) + ((lane >> 4) << 3));
    uint32_t b_ko = (uint32_t)(((lane >> 3) & 1) * 8);

    float acc[4][4][4];
#pragma unroll
    for (int i = 0; i < 4; i++)
#pragma unroll
        for (int j = 0; j < 4; j++)
#pragma unroll
            for (int r = 0; r < 4; r++) acc[i][j][r] = 0.0f;

    // prologue: chunks 0,1 into stages 0,1
#pragma unroll
    for (int c = 0; c < 2; c++) {
        uint32_t st = sb + c * STAGE_B;
        int kc = c * GBK;
        load_tile(st,              g_ahi, bm, kc, tid);
        load_tile(st + TILE_B,     g_alo, bm, kc, tid);
        load_tile(st + 2 * TILE_B, Bhi,   bn, kc, tid);
        load_tile(st + 3 * TILE_B, Blo,   bn, kc, tid);
        asm volatile("cp.async.commit_group;" ::: "memory");
    }

    for (int c = 0; c < kt; c++) {
        bool more = (c + 2 < kt);
        if (more)
            asm volatile("cp.async.wait_group 1;" ::: "memory");
        else
            asm volatile("cp.async.wait_group 0;" ::: "memory");
        __syncthreads();

        uint32_t st = sb + (c & 1) * STAGE_B;
#pragma unroll
        for (int ks = 0; ks < 2; ks++) {
            uint32_t bhi_f[4][2], blo_f[4][2];
#pragma unroll
            for (int p = 0; p < 2; p++) {
                uint32_t off = ((b_row + p * 16) * PADK + ks * 16 + b_ko) * 2;
                uint32_t r[4];
                ldsm4(r, st + 2 * TILE_B + off);
                bhi_f[2 * p][0] = r[0]; bhi_f[2 * p][1] = r[1];
                bhi_f[2 * p + 1][0] = r[2]; bhi_f[2 * p + 1][1] = r[3];
                ldsm4(r, st + 3 * TILE_B + off);
                blo_f[2 * p][0] = r[0]; blo_f[2 * p][1] = r[1];
                blo_f[2 * p + 1][0] = r[2]; blo_f[2 * p + 1][1] = r[3];
            }
#pragma unroll
            for (int mt = 0; mt < 4; mt++) {
                uint32_t ahi_f[4], alo_f[4];
                uint32_t off = ((a_row + mt * 16) * PADK + ks * 16 + a_ko) * 2;
                ldsm4(ahi_f, st + off);
                ldsm4(alo_f, st + TILE_B + off);
                // term-major: reuse distance on each acc = 4 independent MMAs
#pragma unroll
                for (int nt = 0; nt < 4; nt++) mma_bf16(acc[mt][nt], ahi_f, bhi_f[nt]);
#pragma unroll
                for (int nt = 0; nt < 4; nt++) mma_bf16(acc[mt][nt], ahi_f, blo_f[nt]);
#pragma unroll
                for (int nt = 0; nt < 4; nt++) mma_bf16(acc[mt][nt], alo_f, bhi_f[nt]);
            }
        }
        __syncthreads();   // all warps done reading stage (c&1) before reload

        if (more) {
            uint32_t st2 = sb + ((c + 2) & 1) * STAGE_B;
            int kc = (c + 2) * GBK;
            load_tile(st2,              g_ahi, bm, kc, tid);
            load_tile(st2 + TILE_B,     g_alo, bm, kc, tid);
            load_tile(st2 + 2 * TILE_B, Bhi,   bn, kc, tid);
            load_tile(st2 + 3 * TILE_B, Blo,   bn, kc, tid);
            asm volatile("cp.async.commit_group;" ::: "memory");
        }
    }

    // epilogue
#pragma unroll
    for (int mt = 0; mt < 4; mt++) {
        int r0 = bm + wm * 64 + mt * 16 + (lane >> 2);
#pragma unroll
        for (int nt = 0; nt < 4; nt++) {
            int cidx = bn + wn * 32 + nt * 8 + (lane & 3) * 2;
            float* p0 = C + (size_t)r0 * LDC_ + cidx;
            float* p1 = C + (size_t)(r0 + 8) * LDC_ + cidx;
            *(float2*)p0 = make_float2(acc[mt][nt][0], acc[mt][nt][1]);
            *(float2*)p1 = make_float2(acc[mt][nt][2], acc[mt][nt][3]);
        }
    }
}

// ---------------------------------------------------------------------------
// per-token inverse L2 norm of k only (qinv computed inside k_attn_ln).
// ---------------------------------------------------------------------------
__global__ __launch_bounds__(256) void k_norms() {
    int t = blockIdx.x;
    int tid = threadIdx.x;
    const float* krow = g_qkv + (size_t)t * QKVD + EE;
    float k0 = krow[tid], k1 = krow[tid + 256], k2 = krow[tid + 512];
    float sk = k0 * k0 + k1 * k1 + k2 * k2;
    float dummy = 0.0f;
    block_reduce2_256(sk, dummy);
    if (tid == 0) g_kinv[t] = 1.0f / fmaxf(sqrtf(sk), 1e-12f);
}

// ---------------------------------------------------------------------------
// kv partial sums: kv[b,e] = sum_t phi_k[t,e] * v[t,e]
// ---------------------------------------------------------------------------
__global__ __launch_bounds__(256) void k_kvred() {
    int b = blockIdx.y;
    int chunk = blockIdx.x;
    int tid = threadIdx.x;
    float a0 = 0.f, a1 = 0.f, a2 = 0.f;
    int t0 = b * NN + chunk * 128;
    for (int i = 0; i < 128; i++) {
        const float* row = g_qkv + (size_t)(t0 + i) * QKVD;
        const float* kr = row + EE;
        const float* vr = row + 2 * EE;
        float ki = g_kinv[t0 + i];
        a0 += (kr[tid] * ki) * vr[tid];
        a1 += (kr[tid + 256] * ki) * vr[tid + 256];
        a2 += (kr[tid + 512] * ki) * vr[tid + 512];
    }
    float* dst = g_kvpart + ((size_t)chunk * BQ + b) * EE;
    dst[tid] = a0; dst[tid + 256] = a1; dst[tid + 512] = a2;
}

__global__ __launch_bounds__(256) void k_kvsum() {
    int i = blockIdx.x * 256 + threadIdx.x;
    float s = 0.f;
#pragma unroll
    for (int c = 0; c < 32; c++) s += g_kvpart[(size_t)c * BQ * EE + i];
    g_kv[i] = s;
}

// ---------------------------------------------------------------------------
// qinv inline; attn = phi_q * kv[b]; layernorm over E; fused bf16 hi/lo split.
// ---------------------------------------------------------------------------
__global__ __launch_bounds__(256) void k_attn_ln(const float* __restrict__ gam,
                                                 const float* __restrict__ bet) {
    int t = blockIdx.x;
    int b = t >> 12;
    int tid = threadIdx.x;
    const float* qrow = g_qkv + (size_t)t * QKVD;
    const float* kvb = g_kv + b * EE;
    float q0 = qrow[tid], q1 = qrow[tid + 256], q2 = qrow[tid + 512];

    // inline q L2 norm
    float qsq = q0 * q0 + q1 * q1 + q2 * q2;
    float dummy = 0.0f;
    block_reduce2_256(qsq, dummy);
    __shared__ float s_qi;
    if (tid == 0) s_qi = 1.0f / fmaxf(sqrtf(qsq), 1e-12f);
    __syncthreads();
    float qi = s_qi;

    float a0 = (q0 * qi) * kvb[tid];
    float a1 = (q1 * qi) * kvb[tid + 256];
    float a2 = (q2 * qi) * kvb[tid + 512];
    float s = a0 + a1 + a2;
    float sq = a0 * a0 + a1 * a1 + a2 * a2;
    block_reduce2_256(s, sq);
    __shared__ float s_mu, s_rstd;
    if (tid == 0) {
        float mu = s * (1.0f / EE);
        float var = sq * (1.0f / EE) - mu * mu;
        s_mu = mu;
        s_rstd = rsqrtf(var + 1e-5f);
    }
    __syncthreads();
    float mu = s_mu, rstd = s_rstd;
    size_t base = (size_t)t * EE;
    split_store((a0 - mu) * rstd * gam[tid] + bet[tid], g_ahi, g_alo, base + tid);
    split_store((a1 - mu) * rstd * gam[tid + 256] + bet[tid + 256], g_ahi, g_alo, base + tid + 256);
    split_store((a2 - mu) * rstd * gam[tid + 512] + bet[tid + 512], g_ahi, g_alo, base + tid + 512);
}

// ---------------------------------------------------------------------------
extern "C" void kernel_launch(void* const* d_in, const int* in_sizes, int n_in,
                              void* d_out, int out_size) {
    const float* x        = (const float*)d_in[0];
    const float* w_qkv    = (const float*)d_in[1];
    const float* w_proj   = (const float*)d_in[2];
    const float* ln_in_g  = (const float*)d_in[3];
    const float* ln_in_b  = (const float*)d_in[4];
    const float* ln_out_g = (const float*)d_in[5];
    const float* ln_out_b = (const float*)d_in[6];
    float* out = (float*)d_out;

    cudaFuncSetAttribute(k_gemm<QKVD>, cudaFuncAttributeMaxDynamicSharedMemorySize, GSMEM);
    cudaFuncSetAttribute(k_gemm<CC>, cudaFuncAttributeMaxDynamicSharedMemorySize, GSMEM);

    bf16* bqhi; cudaGetSymbolAddress((void**)&bqhi, g_bqhi);
    bf16* bqlo; cudaGetSymbolAddress((void**)&bqlo, g_bqlo);
    bf16* bphi; cudaGetSymbolAddress((void**)&bphi, g_bphi);
    bf16* bplo; cudaGetSymbolAddress((void**)&bplo, g_bplo);
    float* qkv; cudaGetSymbolAddress((void**)&qkv, g_qkv);

    k_ln_in<<<MM, 256>>>(x, ln_in_g, ln_in_b);
    k_wprep<<<dim3(QKVD / 32, CC / 32), 256>>>(w_qkv, QKVD, 0);
    k_wprep<<<dim3(CC / 32, CC / 32), 256>>>(w_proj, CC, 1);
    k_gemm<QKVD><<<dim3(QKVD / GBN, MM / GBM), 256, GSMEM>>>(bqhi, bqlo, qkv);
    k_norms<<<MM, 256>>>();
    k_kvred<<<dim3(32, BQ), 256>>>();
    k_kvsum<<<BQ * EE / 256, 256>>>();
    k_attn_ln<<<MM, 256>>>(ln_out_g, ln_out_b);
    k_gemm<CC><<<dim3(CC / GBN, MM / GBM), 256, GSMEM>>>(bphi, bplo, out);
}

// round 9
// speedup vs baseline: 2.1497x; 1.0056x over previous
#include <cuda_runtime.h>
#include <cuda_bf16.h>
#include <cstdint>

// Problem constants
#define BQ 8
#define NN 4096
#define CC 768
#define EE 768
#define MM (BQ * NN)     // 32768 tokens
#define QKVD (3 * EE)    // 2304

using bf16 = __nv_bfloat16;

// ---------------- device scratch (no allocation allowed) -------------------
__device__ __align__(128) float g_qkv[(size_t)MM * QKVD];   // GEMM1 out (fp32)
__device__ __align__(128) bf16  g_ahi[(size_t)MM * CC];     // A hi
__device__ __align__(128) bf16  g_alo[(size_t)MM * CC];     // A lo
__device__ __align__(128) bf16  g_bqhi[(size_t)QKVD * CC];  // w_qkv^T hi [2304,768]
__device__ __align__(128) bf16  g_bqlo[(size_t)QKVD * CC];
__device__ __align__(128) bf16  g_bphi[(size_t)EE * CC];    // w_proj^T hi [768,768]
__device__ __align__(128) bf16  g_bplo[(size_t)EE * CC];
__device__ float g_kvpart[32 * BQ * EE];
__device__ float g_kv[BQ * EE];
__device__ float g_kinv[MM];

// ---------------------------- helpers --------------------------------------
__device__ __forceinline__ uint32_t smem_u32(const void* p) {
    uint32_t a;
    asm("{ .reg .u64 t; cvta.to.shared.u64 t, %1; cvt.u32.u64 %0, t; }"
        : "=r"(a) : "l"(p));
    return a;
}
__device__ __forceinline__ void cpa16(uint32_t dst, const void* src) {
    asm volatile("cp.async.cg.shared.global [%0], [%1], 16;" :: "r"(dst), "l"(src));
}
__device__ __forceinline__ void ldsm4(uint32_t* r, uint32_t addr) {
    asm volatile("ldmatrix.sync.aligned.m8n8.x4.shared.b16 {%0,%1,%2,%3}, [%4];"
                 : "=r"(r[0]), "=r"(r[1]), "=r"(r[2]), "=r"(r[3]) : "r"(addr));
}
__device__ __forceinline__ void mma_bf16(float* d, const uint32_t* a,
                                         const uint32_t* b) {
    asm volatile(
        "mma.sync.aligned.m16n8k16.row.col.f32.bf16.bf16.f32 "
        "{%0,%1,%2,%3},{%4,%5,%6,%7},{%8,%9},{%0,%1,%2,%3};"
        : "+f"(d[0]), "+f"(d[1]), "+f"(d[2]), "+f"(d[3])
        : "r"(a[0]), "r"(a[1]), "r"(a[2]), "r"(a[3]), "r"(b[0]), "r"(b[1]));
}

// ---------------------------------------------------------------------------
// Block-wide reduction of two floats across 256 threads (result on tid 0).
// ---------------------------------------------------------------------------
__device__ __forceinline__ void block_reduce2_256(float& a, float& b) {
    __shared__ float sa[8], sb[8];
    int lane = threadIdx.x & 31;
    int w = threadIdx.x >> 5;
#pragma unroll
    for (int o = 16; o > 0; o >>= 1) {
        a += __shfl_down_sync(0xffffffffu, a, o);
        b += __shfl_down_sync(0xffffffffu, b, o);
    }
    if (lane == 0) { sa[w] = a; sb[w] = b; }
    __syncthreads();
    if (w == 0) {
        a = (lane < 8) ? sa[lane] : 0.0f;
        b = (lane < 8) ? sb[lane] : 0.0f;
#pragma unroll
        for (int o = 4; o > 0; o >>= 1) {
            a += __shfl_down_sync(0xffu, a, o);
            b += __shfl_down_sync(0xffu, b, o);
        }
    }
}

__device__ __forceinline__ void split_store(float v, bf16* hi, bf16* lo, size_t i) {
    bf16 h = __float2bfloat16(v);
    hi[i] = h;
    lo[i] = __float2bfloat16(v - __bfloat162float(h));
}

// ---------------------------------------------------------------------------
// Kernel 1: layernorm(x) over C, fused fp32 -> bf16 hi/lo split.
// ---------------------------------------------------------------------------
__global__ __launch_bounds__(256) void k_ln_in(const float* __restrict__ x,
                                               const float* __restrict__ gam,
                                               const float* __restrict__ bet) {
    int t = blockIdx.x;
    int tid = threadIdx.x;
    const float* row = x + (size_t)t * CC;
    float v0 = row[tid], v1 = row[tid + 256], v2 = row[tid + 512];
    float s = v0 + v1 + v2;
    float sq = v0 * v0 + v1 * v1 + v2 * v2;
    block_reduce2_256(s, sq);
    __shared__ float s_mu, s_rstd;
    if (tid == 0) {
        float mu = s * (1.0f / CC);
        float var = sq * (1.0f / CC) - mu * mu;
        s_mu = mu;
        s_rstd = rsqrtf(var + 1e-5f);
    }
    __syncthreads();
    float mu = s_mu, rstd = s_rstd;
    size_t base = (size_t)t * CC;
    split_store((v0 - mu) * rstd * gam[tid] + bet[tid], g_ahi, g_alo, base + tid);
    split_store((v1 - mu) * rstd * gam[tid + 256] + bet[tid + 256], g_ahi, g_alo, base + tid + 256);
    split_store((v2 - mu) * rstd * gam[tid + 512] + bet[tid + 512], g_ahi, g_alo, base + tid + 512);
}

// ---------------------------------------------------------------------------
// Weight prep: w[K,N] fp32 -> hi/lo bf16 transposed [N,K].
// ---------------------------------------------------------------------------
__global__ __launch_bounds__(256) void k_wprep(const float* __restrict__ w,
                                               int N, int which) {
    __shared__ float t[32][33];
    bf16* bhi = which ? g_bphi : g_bqhi;
    bf16* blo = which ? g_bplo : g_bqlo;
    const int K = CC;
    int n0 = blockIdx.x * 32, k0 = blockIdx.y * 32;
    int tx = threadIdx.x & 31, ty = threadIdx.x >> 5;
    for (int i = ty; i < 32; i += 8) t[i][tx] = w[(size_t)(k0 + i) * N + n0 + tx];
    __syncthreads();
    for (int i = ty; i < 32; i += 8) {
        float v = t[tx][i];  // element (k0+tx, n0+i)
        size_t o = (size_t)(n0 + i) * K + k0 + tx;
        bf16 h = __float2bfloat16(v);
        bhi[o] = h;
        blo[o] = __float2bfloat16(v - __bfloat162float(h));
    }
}

// ---------------------------------------------------------------------------
// mma.sync bf16 GEMM with 3-term hi/lo compensation.
// C[M,NT] = A[M,768] @ B^T   (A = g_ahi/g_alo, B[n,k] hi/lo)
// CTA 128x128, BK=32, 2-stage cp.async, 2 CTAs/SM. 8 warps: 2(M) x 4(N),
// warp tile 64x32. Smem rows padded to 40 bf16 (80B) -> conflict-free ldmatrix.
// Single-barrier mainloop: wait -> sync -> prefetch c+1 -> compute c.
// ---------------------------------------------------------------------------
#define GBM 128
#define GBN 128
#define GBK 32
#define PADK 40
#define TILE_B (128 * PADK * 2)       // 10240 bytes per 128x32 tile
#define STAGE_B (4 * TILE_B)          // Ahi, Alo, Bhi, Blo
#define NSTG 2
#define GSMEM (NSTG * STAGE_B)        // 81920 bytes -> 2 CTAs/SM

__device__ __forceinline__ void load_tile(uint32_t dst, const bf16* __restrict__ g,
                                          int row0, int kc, int tid) {
#pragma unroll
    for (int i = 0; i < 2; i++) {
        int idx = tid + i * 256;
        int r = idx >> 2, seg = idx & 3;
        cpa16(dst + (uint32_t)(r * PADK + seg * 8) * 2,
              g + (size_t)(row0 + r) * CC + kc + seg * 8);
    }
}

template <int LDC_>
__global__ __launch_bounds__(256, 2) void k_gemm(const bf16* __restrict__ Bhi,
                                                 const bf16* __restrict__ Blo,
                                                 float* __restrict__ C) {
    extern __shared__ char dsm[];
    uint32_t sb = smem_u32(dsm);
    int tid = threadIdx.x, lane = tid & 31, wid = tid >> 5;
    int wm = wid >> 2, wn = wid & 3;               // warp grid 2 x 4
    int bm = blockIdx.y * GBM, bn = blockIdx.x * GBN;
    const int kt = CC / GBK;                       // 24 chunks

    // ldmatrix per-thread row/col offsets
    uint32_t a_row = (uint32_t)(wm * 64 + (lane & 15));
    uint32_t a_ko = (uint32_t)((lane >> 4) * 8);
    uint32_t b_row = (uint32_t)(wn * 32 + (lane & 7) + ((lane >> 4) << 3));
    uint32_t b_ko = (uint32_t)(((lane >> 3) & 1) * 8);

    float acc[4][4][4];
#pragma unroll
    for (int i = 0; i < 4; i++)
#pragma unroll
        for (int j = 0; j < 4; j++)
#pragma unroll
            for (int r = 0; r < 4; r++) acc[i][j][r] = 0.0f;

    // prologue: chunk 0 into stage 0
    {
        load_tile(sb,              g_ahi, bm, 0, tid);
        load_tile(sb + TILE_B,     g_alo, bm, 0, tid);
        load_tile(sb + 2 * TILE_B, Bhi,   bn, 0, tid);
        load_tile(sb + 3 * TILE_B, Blo,   bn, 0, tid);
        asm volatile("cp.async.commit_group;" ::: "memory");
    }

    for (int c = 0; c < kt; c++) {
        asm volatile("cp.async.wait_group 0;" ::: "memory");
        __syncthreads();   // chunk c visible to all; all warps past stage (c+1)&1

        if (c + 1 < kt) {  // prefetch chunk c+1 into the stage freed at iter c-1
            uint32_t st2 = sb + ((c + 1) & 1) * STAGE_B;
            int kc = (c + 1) * GBK;
            load_tile(st2,              g_ahi, bm, kc, tid);
            load_tile(st2 + TILE_B,     g_alo, bm, kc, tid);
            load_tile(st2 + 2 * TILE_B, Bhi,   bn, kc, tid);
            load_tile(st2 + 3 * TILE_B, Blo,   bn, kc, tid);
            asm volatile("cp.async.commit_group;" ::: "memory");
        }

        uint32_t st = sb + (c & 1) * STAGE_B;
#pragma unroll
        for (int ks = 0; ks < 2; ks++) {
            uint32_t bhi_f[4][2], blo_f[4][2];
#pragma unroll
            for (int p = 0; p < 2; p++) {
                uint32_t off = ((b_row + p * 16) * PADK + ks * 16 + b_ko) * 2;
                uint32_t r[4];
                ldsm4(r, st + 2 * TILE_B + off);
                bhi_f[2 * p][0] = r[0]; bhi_f[2 * p][1] = r[1];
                bhi_f[2 * p + 1][0] = r[2]; bhi_f[2 * p + 1][1] = r[3];
                ldsm4(r, st + 3 * TILE_B + off);
                blo_f[2 * p][0] = r[0]; blo_f[2 * p][1] = r[1];
                blo_f[2 * p + 1][0] = r[2]; blo_f[2 * p + 1][1] = r[3];
            }
#pragma unroll
            for (int mt = 0; mt < 4; mt++) {
                uint32_t ahi_f[4], alo_f[4];
                uint32_t off = ((a_row + mt * 16) * PADK + ks * 16 + a_ko) * 2;
                ldsm4(ahi_f, st + off);
                ldsm4(alo_f, st + TILE_B + off);
#pragma unroll
                for (int nt = 0; nt < 4; nt++) mma_bf16(acc[mt][nt], ahi_f, bhi_f[nt]);
#pragma unroll
                for (int nt = 0; nt < 4; nt++) mma_bf16(acc[mt][nt], ahi_f, blo_f[nt]);
#pragma unroll
                for (int nt = 0; nt < 4; nt++) mma_bf16(acc[mt][nt], alo_f, bhi_f[nt]);
            }
        }
    }

    // epilogue
#pragma unroll
    for (int mt = 0; mt < 4; mt++) {
        int r0 = bm + wm * 64 + mt * 16 + (lane >> 2);
#pragma unroll
        for (int nt = 0; nt < 4; nt++) {
            int cidx = bn + wn * 32 + nt * 8 + (lane & 3) * 2;
            float* p0 = C + (size_t)r0 * LDC_ + cidx;
            float* p1 = C + (size_t)(r0 + 8) * LDC_ + cidx;
            *(float2*)p0 = make_float2(acc[mt][nt][0], acc[mt][nt][1]);
            *(float2*)p1 = make_float2(acc[mt][nt][2], acc[mt][nt][3]);
        }
    }
}

// ---------------------------------------------------------------------------
// per-token inverse L2 norm of k only (qinv computed inside k_attn_ln).
// ---------------------------------------------------------------------------
__global__ __launch_bounds__(256) void k_norms() {
    int t = blockIdx.x;
    int tid = threadIdx.x;
    const float* krow = g_qkv + (size_t)t * QKVD + EE;
    float k0 = krow[tid], k1 = krow[tid + 256], k2 = krow[tid + 512];
    float sk = k0 * k0 + k1 * k1 + k2 * k2;
    float dummy = 0.0f;
    block_reduce2_256(sk, dummy);
    if (tid == 0) g_kinv[t] = 1.0f / fmaxf(sqrtf(sk), 1e-12f);
}

// ---------------------------------------------------------------------------
// kv partial sums: kv[b,e] = sum_t phi_k[t,e] * v[t,e]
// ---------------------------------------------------------------------------
__global__ __launch_bounds__(256) void k_kvred() {
    int b = blockIdx.y;
    int chunk = blockIdx.x;
    int tid = threadIdx.x;
    float a0 = 0.f, a1 = 0.f, a2 = 0.f;
    int t0 = b * NN + chunk * 128;
    for (int i = 0; i < 128; i++) {
        const float* row = g_qkv + (size_t)(t0 + i) * QKVD;
        const float* kr = row + EE;
        const float* vr = row + 2 * EE;
        float ki = g_kinv[t0 + i];
        a0 += (kr[tid] * ki) * vr[tid];
        a1 += (kr[tid + 256] * ki) * vr[tid + 256];
        a2 += (kr[tid + 512] * ki) * vr[tid + 512];
    }
    float* dst = g_kvpart + ((size_t)chunk * BQ + b) * EE;
    dst[tid] = a0; dst[tid + 256] = a1; dst[tid + 512] = a2;
}

__global__ __launch_bounds__(256) void k_kvsum() {
    int i = blockIdx.x * 256 + threadIdx.x;
    float s = 0.f;
#pragma unroll
    for (int c = 0; c < 32; c++) s += g_kvpart[(size_t)c * BQ * EE + i];
    g_kv[i] = s;
}

// ---------------------------------------------------------------------------
// qinv inline; attn = phi_q * kv[b]; layernorm over E; fused bf16 hi/lo split.
// ---------------------------------------------------------------------------
__global__ __launch_bounds__(256) void k_attn_ln(const float* __restrict__ gam,
                                                 const float* __restrict__ bet) {
    int t = blockIdx.x;
    int b = t >> 12;
    int tid = threadIdx.x;
    const float* qrow = g_qkv + (size_t)t * QKVD;
    const float* kvb = g_kv + b * EE;
    float q0 = qrow[tid], q1 = qrow[tid + 256], q2 = qrow[tid + 512];

    // inline q L2 norm
    float qsq = q0 * q0 + q1 * q1 + q2 * q2;
    float dummy = 0.0f;
    block_reduce2_256(qsq, dummy);
    __shared__ float s_qi;
    if (tid == 0) s_qi = 1.0f / fmaxf(sqrtf(qsq), 1e-12f);
    __syncthreads();
    float qi = s_qi;

    float a0 = (q0 * qi) * kvb[tid];
    float a1 = (q1 * qi) * kvb[tid + 256];
    float a2 = (q2 * qi) * kvb[tid + 512];
    float s = a0 + a1 + a2;
    float sq = a0 * a0 + a1 * a1 + a2 * a2;
    block_reduce2_256(s, sq);
    __shared__ float s_mu, s_rstd;
    if (tid == 0) {
        float mu = s * (1.0f / EE);
        float var = sq * (1.0f / EE) - mu * mu;
        s_mu = mu;
        s_rstd = rsqrtf(var + 1e-5f);
    }
    __syncthreads();
    float mu = s_mu, rstd = s_rstd;
    size_t base = (size_t)t * EE;
    split_store((a0 - mu) * rstd * gam[tid] + bet[tid], g_ahi, g_alo, base + tid);
    split_store((a1 - mu) * rstd * gam[tid + 256] + bet[tid + 256], g_ahi, g_alo, base + tid + 256);
    split_store((a2 - mu) * rstd * gam[tid + 512] + bet[tid + 512], g_ahi, g_alo, base + tid + 512);
}

// ---------------------------------------------------------------------------
extern "C" void kernel_launch(void* const* d_in, const int* in_sizes, int n_in,
                              void* d_out, int out_size) {
    const float* x        = (const float*)d_in[0];
    const float* w_qkv    = (const float*)d_in[1];
    const float* w_proj   = (const float*)d_in[2];
    const float* ln_in_g  = (const float*)d_in[3];
    const float* ln_in_b  = (const float*)d_in[4];
    const float* ln_out_g = (const float*)d_in[5];
    const float* ln_out_b = (const float*)d_in[6];
    float* out = (float*)d_out;

    cudaFuncSetAttribute(k_gemm<QKVD>, cudaFuncAttributeMaxDynamicSharedMemorySize, GSMEM);
    cudaFuncSetAttribute(k_gemm<CC>, cudaFuncAttributeMaxDynamicSharedMemorySize, GSMEM);

    bf16* bqhi; cudaGetSymbolAddress((void**)&bqhi, g_bqhi);
    bf16* bqlo; cudaGetSymbolAddress((void**)&bqlo, g_bqlo);
    bf16* bphi; cudaGetSymbolAddress((void**)&bphi, g_bphi);
    bf16* bplo; cudaGetSymbolAddress((void**)&bplo, g_bplo);
    float* qkv; cudaGetSymbolAddress((void**)&qkv, g_qkv);

    k_ln_in<<<MM, 256>>>(x, ln_in_g, ln_in_b);
    k_wprep<<<dim3(QKVD / 32, CC / 32), 256>>>(w_qkv, QKVD, 0);
    k_wprep<<<dim3(CC / 32, CC / 32), 256>>>(w_proj, CC, 1);
    k_gemm<QKVD><<<dim3(QKVD / GBN, MM / GBM), 256, GSMEM>>>(bqhi, bqlo, qkv);
    k_norms<<<MM, 256>>>();
    k_kvred<<<dim3(32, BQ), 256>>>();
    k_kvsum<<<BQ * EE / 256, 256>>>();
    k_attn_ln<<<MM, 256>>>(ln_out_g, ln_out_b);
    k_gemm<CC><<<dim3(CC / GBN, MM / GBM), 256, GSMEM>>>(bphi, bplo, out);
}

// round 10
// speedup vs baseline: 2.7843x; 1.2952x over previous
#include <cuda_runtime.h>
#include <cuda_bf16.h>
#include <cstdint>

// Problem constants
#define BQ 8
#define NN 4096
#define CC 768
#define EE 768
#define MM (BQ * NN)     // 32768 tokens
#define QKVD (3 * EE)    // 2304

// ---------------- device scratch (no allocation allowed) -------------------
__device__ __align__(128) float  g_qkv[(size_t)MM * QKVD];    // GEMM1 out fp32
__device__ __align__(128) int8_t g_aq1[(size_t)MM * CC];      // A quant level 1
__device__ __align__(128) int8_t g_aq2[(size_t)MM * CC];      // A quant level 2
__device__ __align__(128) float  g_asc[MM];                   // A row scales
__device__ __align__(128) int8_t g_bq1q[(size_t)QKVD * CC];   // w_qkv^T q1 [2304,768]
__device__ __align__(128) int8_t g_bq2q[(size_t)QKVD * CC];
__device__ __align__(128) float  g_bscq[QKVD];
__device__ __align__(128) int8_t g_bq1p[(size_t)EE * CC];     // w_proj^T q1 [768,768]
__device__ __align__(128) int8_t g_bq2p[(size_t)EE * CC];
__device__ __align__(128) float  g_bscp[EE];
__device__ float g_kvpart[32 * BQ * EE];
__device__ float g_kv[BQ * EE];
__device__ float g_kinv[MM];

#define QSCL2 254.0f

// ---------------------------- helpers --------------------------------------
__device__ __forceinline__ uint32_t smem_u32(const void* p) {
    uint32_t a;
    asm("{ .reg .u64 t; cvta.to.shared.u64 t, %1; cvt.u32.u64 %0, t; }"
        : "=r"(a) : "l"(p));
    return a;
}
__device__ __forceinline__ void cpa16(uint32_t dst, const void* src) {
    asm volatile("cp.async.cg.shared.global [%0], [%1], 16;" :: "r"(dst), "l"(src));
}
__device__ __forceinline__ void ldsm4(uint32_t* r, uint32_t addr) {
    asm volatile("ldmatrix.sync.aligned.m8n8.x4.shared.b16 {%0,%1,%2,%3}, [%4];"
                 : "=r"(r[0]), "=r"(r[1]), "=r"(r[2]), "=r"(r[3]) : "r"(addr));
}
__device__ __forceinline__ void mma_s8(int* d, const uint32_t* a,
                                       const uint32_t* b) {
    asm volatile(
        "mma.sync.aligned.m16n8k32.row.col.s32.s8.s8.s32 "
        "{%0,%1,%2,%3},{%4,%5,%6,%7},{%8,%9},{%0,%1,%2,%3};"
        : "+r"(d[0]), "+r"(d[1]), "+r"(d[2]), "+r"(d[3])
        : "r"(a[0]), "r"(a[1]), "r"(a[2]), "r"(a[3]), "r"(b[0]), "r"(b[1]));
}

// ---------------------------------------------------------------------------
// Block-wide reductions (256 threads). Result on tid 0.
// ---------------------------------------------------------------------------
__device__ __forceinline__ void block_reduce2_256(float& a, float& b) {
    __shared__ float sa[8], sb[8];
    int lane = threadIdx.x & 31;
    int w = threadIdx.x >> 5;
#pragma unroll
    for (int o = 16; o > 0; o >>= 1) {
        a += __shfl_down_sync(0xffffffffu, a, o);
        b += __shfl_down_sync(0xffffffffu, b, o);
    }
    if (lane == 0) { sa[w] = a; sb[w] = b; }
    __syncthreads();
    if (w == 0) {
        a = (lane < 8) ? sa[lane] : 0.0f;
        b = (lane < 8) ? sb[lane] : 0.0f;
#pragma unroll
        for (int o = 4; o > 0; o >>= 1) {
            a += __shfl_down_sync(0xffu, a, o);
            b += __shfl_down_sync(0xffu, b, o);
        }
    }
}

__device__ __forceinline__ float block_rmax_256(float m) {
    __shared__ float sm[8];
    __syncthreads();   // protect sm reuse across successive reductions
    int lane = threadIdx.x & 31;
    int w = threadIdx.x >> 5;
#pragma unroll
    for (int o = 16; o > 0; o >>= 1)
        m = fmaxf(m, __shfl_down_sync(0xffffffffu, m, o));
    if (lane == 0) sm[w] = m;
    __syncthreads();
    if (w == 0) {
        m = (lane < 8) ? sm[lane] : 0.0f;
#pragma unroll
        for (int o = 4; o > 0; o >>= 1)
            m = fmaxf(m, __shfl_down_sync(0xffu, m, o));
    }
    return m;
}

// quantize y with scale sa: y = sa*(q1 + q2/254)
__device__ __forceinline__ void quant_store(float y, float inv, size_t i) {
    int q1 = __float2int_rn(y * inv);
    float r = fmaf(y, inv, -(float)q1);
    int q2 = __float2int_rn(r * QSCL2);
    g_aq1[i] = (int8_t)q1;
    g_aq2[i] = (int8_t)q2;
}

// ---------------------------------------------------------------------------
// Kernel 1: layernorm(x) over C, fused int8 2-level quantization.
// ---------------------------------------------------------------------------
__global__ __launch_bounds__(256) void k_ln_in(const float* __restrict__ x,
                                               const float* __restrict__ gam,
                                               const float* __restrict__ bet) {
    int t = blockIdx.x;
    int tid = threadIdx.x;
    const float* row = x + (size_t)t * CC;
    float v0 = row[tid], v1 = row[tid + 256], v2 = row[tid + 512];
    float s = v0 + v1 + v2;
    float sq = v0 * v0 + v1 * v1 + v2 * v2;
    block_reduce2_256(s, sq);
    __shared__ float s_mu, s_rstd;
    if (tid == 0) {
        float mu = s * (1.0f / CC);
        float var = sq * (1.0f / CC) - mu * mu;
        s_mu = mu;
        s_rstd = rsqrtf(var + 1e-5f);
    }
    __syncthreads();
    float mu = s_mu, rstd = s_rstd;
    float y0 = (v0 - mu) * rstd * gam[tid] + bet[tid];
    float y1 = (v1 - mu) * rstd * gam[tid + 256] + bet[tid + 256];
    float y2 = (v2 - mu) * rstd * gam[tid + 512] + bet[tid + 512];

    float m = fmaxf(fmaxf(fabsf(y0), fabsf(y1)), fabsf(y2));
    m = block_rmax_256(m);
    __shared__ float s_inv;
    if (tid == 0) {
        float sa = fmaxf(m, 1e-30f) * (1.0f / 127.0f);
        g_asc[t] = sa;
        s_inv = 1.0f / sa;
    }
    __syncthreads();
    float inv = s_inv;
    size_t base = (size_t)t * CC;
    quant_store(y0, inv, base + tid);
    quant_store(y1, inv, base + tid + 256);
    quant_store(y2, inv, base + tid + 512);
}

// ---------------------------------------------------------------------------
// Weight prep: per-output-column max, then quantized transpose.
// ---------------------------------------------------------------------------
__global__ __launch_bounds__(256) void k_wmax(const float* __restrict__ w,
                                              int N, float* __restrict__ bsc) {
    int n = blockIdx.x * 256 + threadIdx.x;
    float m = 0.0f;
    for (int k = 0; k < CC; k++) m = fmaxf(m, fabsf(w[(size_t)k * N + n]));
    bsc[n] = fmaxf(m, 1e-30f) * (1.0f / 127.0f);
}

__global__ __launch_bounds__(256) void k_wquant(const float* __restrict__ w,
                                                int N, const float* __restrict__ bsc,
                                                int8_t* __restrict__ q1,
                                                int8_t* __restrict__ q2) {
    __shared__ float t[32][33];
    int n0 = blockIdx.x * 32, k0 = blockIdx.y * 32;
    int tx = threadIdx.x & 31, ty = threadIdx.x >> 5;
    for (int i = ty; i < 32; i += 8) t[i][tx] = w[(size_t)(k0 + i) * N + n0 + tx];
    __syncthreads();
    for (int i = ty; i < 32; i += 8) {
        float v = t[tx][i];  // element (k0+tx, n0+i)
        int n = n0 + i;
        float inv = 1.0f / bsc[n];
        int a = __float2int_rn(v * inv);
        float r = fmaf(v, inv, -(float)a);
        int b = __float2int_rn(r * QSCL2);
        size_t o = (size_t)n * CC + k0 + tx;
        q1[o] = (int8_t)a;
        q2[o] = (int8_t)b;
    }
}

// ---------------------------------------------------------------------------
// INT8 IMMA GEMM: C[M,NT] = sa[m]*sb[n]*(accH + accM/254)
// A = g_aq1/g_aq2 [M,768], B = q1/q2 [NT,768]. CTA 64x128, BK=64, 2 stages,
// 2 CTAs/SM. 8 warps 2(M) x 4(N); warp tile 32x32, two s32 acc sets.
// Rows padded to 80B -> conflict-free ldmatrix.
// ---------------------------------------------------------------------------
#define IBM 64
#define IBN 128
#define IBK 64
#define IPITCH 80
#define A_TILE (IBM * IPITCH)               // 5120
#define B_TILE (IBN * IPITCH)               // 10240
#define ISTAGE (2 * A_TILE + 2 * B_TILE)    // 30720
#define IGSMEM (2 * ISTAGE)                 // 61440

template <int ROWS>
__device__ __forceinline__ void load_i8_tile(uint32_t dst,
                                             const int8_t* __restrict__ g,
                                             int row0, int kc, int tid) {
#pragma unroll
    for (int i = 0; i < ROWS / 64; i++) {
        int idx = tid + i * 256;
        int r = idx >> 2, seg = idx & 3;
        cpa16(dst + (uint32_t)(r * IPITCH + seg * 16),
              g + (size_t)(row0 + r) * CC + kc + seg * 16);
    }
}

__device__ __forceinline__ void load_chunk_i8(uint32_t st, int bm, int bn, int kc,
                                              int tid, const int8_t* Bq1,
                                              const int8_t* Bq2) {
    load_i8_tile<64>(st,                       g_aq1, bm, kc, tid);
    load_i8_tile<64>(st + A_TILE,              g_aq2, bm, kc, tid);
    load_i8_tile<128>(st + 2 * A_TILE,         Bq1,   bn, kc, tid);
    load_i8_tile<128>(st + 2 * A_TILE + B_TILE, Bq2,  bn, kc, tid);
}

template <int LDC_>
__global__ __launch_bounds__(256, 2) void k_gemm_i8(const int8_t* __restrict__ Bq1,
                                                    const int8_t* __restrict__ Bq2,
                                                    const float* __restrict__ bsc,
                                                    float* __restrict__ C) {
    extern __shared__ char dsm[];
    uint32_t sb = smem_u32(dsm);
    int tid = threadIdx.x, lane = tid & 31, wid = tid >> 5;
    int wm = wid >> 2, wn = wid & 3;          // 2 x 4 warp grid
    int bm = blockIdx.y * IBM, bn = blockIdx.x * IBN;
    const int kt = CC / IBK;                  // 12

    uint32_t lrow = (uint32_t)(lane & 15);
    uint32_t lboff = (uint32_t)((lane >> 4) * 16);

    int accH[2][4][4], accM[2][4][4];
#pragma unroll
    for (int i = 0; i < 2; i++)
#pragma unroll
        for (int j = 0; j < 4; j++)
#pragma unroll
            for (int r = 0; r < 4; r++) { accH[i][j][r] = 0; accM[i][j][r] = 0; }

    // prologue: chunk 0 into stage 0
    load_chunk_i8(sb, bm, bn, 0, tid, Bq1, Bq2);
    asm volatile("cp.async.commit_group;" ::: "memory");

    for (int c = 0; c < kt; c++) {
        asm volatile("cp.async.wait_group 0;" ::: "memory");
        __syncthreads();

        if (c + 1 < kt) {
            load_chunk_i8(sb + ((c + 1) & 1) * ISTAGE, bm, bn, (c + 1) * IBK,
                          tid, Bq1, Bq2);
            asm volatile("cp.async.commit_group;" ::: "memory");
        }

        uint32_t st = sb + (c & 1) * ISTAGE;
#pragma unroll
        for (int ks = 0; ks < 2; ks++) {
            // B fragments: q1 and q2, 4 n-tiles of 8
            uint32_t b1f[4][2], b2f[4][2];
#pragma unroll
            for (int p = 0; p < 2; p++) {
                uint32_t addr = st + 2 * A_TILE +
                                (uint32_t)(wn * 32 + p * 16 + lrow) * IPITCH +
                                (uint32_t)(ks * 32) + lboff;
                uint32_t r[4];
                ldsm4(r, addr);
                b1f[2 * p][0] = r[0]; b1f[2 * p][1] = r[2];
                b1f[2 * p + 1][0] = r[1]; b1f[2 * p + 1][1] = r[3];
                ldsm4(r, addr + B_TILE);
                b2f[2 * p][0] = r[0]; b2f[2 * p][1] = r[2];
                b2f[2 * p + 1][0] = r[1]; b2f[2 * p + 1][1] = r[3];
            }
#pragma unroll
            for (int mt = 0; mt < 2; mt++) {
                uint32_t a1[4], a2[4];
                uint32_t aaddr = st +
                                 (uint32_t)(wm * 32 + mt * 16 + lrow) * IPITCH +
                                 (uint32_t)(ks * 32) + lboff;
                ldsm4(a1, aaddr);
                ldsm4(a2, aaddr + A_TILE);
#pragma unroll
                for (int nt = 0; nt < 4; nt++) mma_s8(accH[mt][nt], a1, b1f[nt]);
#pragma unroll
                for (int nt = 0; nt < 4; nt++) mma_s8(accM[mt][nt], a1, b2f[nt]);
#pragma unroll
                for (int nt = 0; nt < 4; nt++) mma_s8(accM[mt][nt], a2, b1f[nt]);
            }
        }
    }

    // epilogue: dequantize and store fp32
#pragma unroll
    for (int mt = 0; mt < 2; mt++) {
        int r0 = bm + wm * 32 + mt * 16 + (lane >> 2);
        float sa0 = g_asc[r0], sa1 = g_asc[r0 + 8];
#pragma unroll
        for (int nt = 0; nt < 4; nt++) {
            int cidx = bn + wn * 32 + nt * 8 + (lane & 3) * 2;
            float sb0 = bsc[cidx], sb1 = bsc[cidx + 1];
            const int* h = accH[mt][nt];
            const int* m = accM[mt][nt];
            float v00 = sa0 * sb0 * ((float)h[0] + (float)m[0] * (1.0f / QSCL2));
            float v01 = sa0 * sb1 * ((float)h[1] + (float)m[1] * (1.0f / QSCL2));
            float v10 = sa1 * sb0 * ((float)h[2] + (float)m[2] * (1.0f / QSCL2));
            float v11 = sa1 * sb1 * ((float)h[3] + (float)m[3] * (1.0f / QSCL2));
            *(float2*)(C + (size_t)r0 * LDC_ + cidx) = make_float2(v00, v01);
            *(float2*)(C + (size_t)(r0 + 8) * LDC_ + cidx) = make_float2(v10, v11);
        }
    }
}

// ---------------------------------------------------------------------------
// per-token inverse L2 norm of k only (qinv computed inside k_attn_ln).
// ---------------------------------------------------------------------------
__global__ __launch_bounds__(256) void k_norms() {
    int t = blockIdx.x;
    int tid = threadIdx.x;
    const float* krow = g_qkv + (size_t)t * QKVD + EE;
    float k0 = krow[tid], k1 = krow[tid + 256], k2 = krow[tid + 512];
    float sk = k0 * k0 + k1 * k1 + k2 * k2;
    float dummy = 0.0f;
    block_reduce2_256(sk, dummy);
    if (tid == 0) g_kinv[t] = 1.0f / fmaxf(sqrtf(sk), 1e-12f);
}

// ---------------------------------------------------------------------------
// kv partial sums: kv[b,e] = sum_t phi_k[t,e] * v[t,e]
// ---------------------------------------------------------------------------
__global__ __launch_bounds__(256) void k_kvred() {
    int b = blockIdx.y;
    int chunk = blockIdx.x;
    int tid = threadIdx.x;
    float a0 = 0.f, a1 = 0.f, a2 = 0.f;
    int t0 = b * NN + chunk * 128;
    for (int i = 0; i < 128; i++) {
        const float* row = g_qkv + (size_t)(t0 + i) * QKVD;
        const float* kr = row + EE;
        const float* vr = row + 2 * EE;
        float ki = g_kinv[t0 + i];
        a0 += (kr[tid] * ki) * vr[tid];
        a1 += (kr[tid + 256] * ki) * vr[tid + 256];
        a2 += (kr[tid + 512] * ki) * vr[tid + 512];
    }
    float* dst = g_kvpart + ((size_t)chunk * BQ + b) * EE;
    dst[tid] = a0; dst[tid + 256] = a1; dst[tid + 512] = a2;
}

__global__ __launch_bounds__(256) void k_kvsum() {
    int i = blockIdx.x * 256 + threadIdx.x;
    float s = 0.f;
#pragma unroll
    for (int c = 0; c < 32; c++) s += g_kvpart[(size_t)c * BQ * EE + i];
    g_kv[i] = s;
}

// ---------------------------------------------------------------------------
// qinv inline; attn = phi_q*kv; layernorm over E; fused int8 quantization.
// ---------------------------------------------------------------------------
__global__ __launch_bounds__(256) void k_attn_ln(const float* __restrict__ gam,
                                                 const float* __restrict__ bet) {
    int t = blockIdx.x;
    int b = t >> 12;
    int tid = threadIdx.x;
    const float* qrow = g_qkv + (size_t)t * QKVD;
    const float* kvb = g_kv + b * EE;
    float q0 = qrow[tid], q1 = qrow[tid + 256], q2 = qrow[tid + 512];

    float qsq = q0 * q0 + q1 * q1 + q2 * q2;
    float dummy = 0.0f;
    block_reduce2_256(qsq, dummy);
    __shared__ float s_qi;
    if (tid == 0) s_qi = 1.0f / fmaxf(sqrtf(qsq), 1e-12f);
    __syncthreads();
    float qi = s_qi;

    float a0 = (q0 * qi) * kvb[tid];
    float a1 = (q1 * qi) * kvb[tid + 256];
    float a2 = (q2 * qi) * kvb[tid + 512];
    float s = a0 + a1 + a2;
    float sq = a0 * a0 + a1 * a1 + a2 * a2;
    block_reduce2_256(s, sq);
    __shared__ float s_mu, s_rstd;
    if (tid == 0) {
        float mu = s * (1.0f / EE);
        float var = sq * (1.0f / EE) - mu * mu;
        s_mu = mu;
        s_rstd = rsqrtf(var + 1e-5f);
    }
    __syncthreads();
    float mu = s_mu, rstd = s_rstd;
    float y0 = (a0 - mu) * rstd * gam[tid] + bet[tid];
    float y1 = (a1 - mu) * rstd * gam[tid + 256] + bet[tid + 256];
    float y2 = (a2 - mu) * rstd * gam[tid + 512] + bet[tid + 512];

    float m = fmaxf(fmaxf(fabsf(y0), fabsf(y1)), fabsf(y2));
    m = block_rmax_256(m);
    __shared__ float s_inv;
    if (tid == 0) {
        float sa = fmaxf(m, 1e-30f) * (1.0f / 127.0f);
        g_asc[t] = sa;
        s_inv = 1.0f / sa;
    }
    __syncthreads();
    float inv = s_inv;
    size_t base = (size_t)t * EE;
    quant_store(y0, inv, base + tid);
    quant_store(y1, inv, base + tid + 256);
    quant_store(y2, inv, base + tid + 512);
}

// ---------------------------------------------------------------------------
extern "C" void kernel_launch(void* const* d_in, const int* in_sizes, int n_in,
                              void* d_out, int out_size) {
    const float* x        = (const float*)d_in[0];
    const float* w_qkv    = (const float*)d_in[1];
    const float* w_proj   = (const float*)d_in[2];
    const float* ln_in_g  = (const float*)d_in[3];
    const float* ln_in_b  = (const float*)d_in[4];
    const float* ln_out_g = (const float*)d_in[5];
    const float* ln_out_b = (const float*)d_in[6];
    float* out = (float*)d_out;

    cudaFuncSetAttribute(k_gemm_i8<QKVD>, cudaFuncAttributeMaxDynamicSharedMemorySize, IGSMEM);
    cudaFuncSetAttribute(k_gemm_i8<CC>, cudaFuncAttributeMaxDynamicSharedMemorySize, IGSMEM);

    int8_t* bq1q; cudaGetSymbolAddress((void**)&bq1q, g_bq1q);
    int8_t* bq2q; cudaGetSymbolAddress((void**)&bq2q, g_bq2q);
    float*  bscq; cudaGetSymbolAddress((void**)&bscq, g_bscq);
    int8_t* bq1p; cudaGetSymbolAddress((void**)&bq1p, g_bq1p);
    int8_t* bq2p; cudaGetSymbolAddress((void**)&bq2p, g_bq2p);
    float*  bscp; cudaGetSymbolAddress((void**)&bscp, g_bscp);
    float*  qkv;  cudaGetSymbolAddress((void**)&qkv, g_qkv);

    k_ln_in<<<MM, 256>>>(x, ln_in_g, ln_in_b);
    k_wmax<<<QKVD / 256, 256>>>(w_qkv, QKVD, bscq);
    k_wquant<<<dim3(QKVD / 32, CC / 32), 256>>>(w_qkv, QKVD, bscq, bq1q, bq2q);
    k_wmax<<<CC / 256, 256>>>(w_proj, CC, bscp);
    k_wquant<<<dim3(CC / 32, CC / 32), 256>>>(w_proj, CC, bscp, bq1p, bq2p);
    k_gemm_i8<QKVD><<<dim3(QKVD / IBN, MM / IBM), 256, IGSMEM>>>(bq1q, bq2q, bscq, qkv);
    k_norms<<<MM, 256>>>();
    k_kvred<<<dim3(32, BQ), 256>>>();
    k_kvsum<<<BQ * EE / 256, 256>>>();
    k_attn_ln<<<MM, 256>>>(ln_out_g, ln_out_b);
    k_gemm_i8<CC><<<dim3(CC / IBN, MM / IBM), 256, IGSMEM>>>(bq1p, bq2p, bscp, out);
}

// round 11
// speedup vs baseline: 2.9557x; 1.0615x over previous
#include <cuda_runtime.h>
#include <cuda_bf16.h>
#include <cstdint>

// Problem constants
#define BQ 8
#define NN 4096
#define CC 768
#define EE 768
#define MM (BQ * NN)     // 32768 tokens
#define QKVD (3 * EE)    // 2304

// ---------------- device scratch (no allocation allowed) -------------------
__device__ __align__(128) float  g_qkv[(size_t)MM * QKVD];    // GEMM1 out fp32
__device__ __align__(128) int8_t g_aq1[(size_t)MM * CC];      // A quant level 1
__device__ __align__(128) int8_t g_aq2[(size_t)MM * CC];      // A quant level 2
__device__ __align__(128) float  g_asc[MM];                   // A row scales
__device__ __align__(128) int8_t g_bq1q[(size_t)QKVD * CC];   // w_qkv^T q1 [2304,768]
__device__ __align__(128) int8_t g_bq2q[(size_t)QKVD * CC];
__device__ __align__(128) float  g_bscq[QKVD];
__device__ __align__(128) int8_t g_bq1p[(size_t)EE * CC];     // w_proj^T q1 [768,768]
__device__ __align__(128) int8_t g_bq2p[(size_t)EE * CC];
__device__ __align__(128) float  g_bscp[EE];
__device__ float g_kvpart[32 * BQ * EE];
__device__ float g_kv[BQ * EE];
__device__ float g_kinv[MM];

#define QSCL2 254.0f

// ---------------------------- helpers --------------------------------------
__device__ __forceinline__ uint32_t smem_u32(const void* p) {
    uint32_t a;
    asm("{ .reg .u64 t; cvta.to.shared.u64 t, %1; cvt.u32.u64 %0, t; }"
        : "=r"(a) : "l"(p));
    return a;
}
__device__ __forceinline__ void cpa16(uint32_t dst, const void* src) {
    asm volatile("cp.async.cg.shared.global [%0], [%1], 16;" :: "r"(dst), "l"(src));
}
__device__ __forceinline__ void ldsm4(uint32_t* r, uint32_t addr) {
    asm volatile("ldmatrix.sync.aligned.m8n8.x4.shared.b16 {%0,%1,%2,%3}, [%4];"
                 : "=r"(r[0]), "=r"(r[1]), "=r"(r[2]), "=r"(r[3]) : "r"(addr));
}
__device__ __forceinline__ void mma_s8(int* d, const uint32_t* a,
                                       const uint32_t* b) {
    asm volatile(
        "mma.sync.aligned.m16n8k32.row.col.s32.s8.s8.s32 "
        "{%0,%1,%2,%3},{%4,%5,%6,%7},{%8,%9},{%0,%1,%2,%3};"
        : "+r"(d[0]), "+r"(d[1]), "+r"(d[2]), "+r"(d[3])
        : "r"(a[0]), "r"(a[1]), "r"(a[2]), "r"(a[3]), "r"(b[0]), "r"(b[1]));
}

// ---------------------------------------------------------------------------
// Block-wide reductions (256 threads). Result on tid 0.
// ---------------------------------------------------------------------------
__device__ __forceinline__ void block_reduce2_256(float& a, float& b) {
    __shared__ float sa[8], sb[8];
    int lane = threadIdx.x & 31;
    int w = threadIdx.x >> 5;
#pragma unroll
    for (int o = 16; o > 0; o >>= 1) {
        a += __shfl_down_sync(0xffffffffu, a, o);
        b += __shfl_down_sync(0xffffffffu, b, o);
    }
    if (lane == 0) { sa[w] = a; sb[w] = b; }
    __syncthreads();
    if (w == 0) {
        a = (lane < 8) ? sa[lane] : 0.0f;
        b = (lane < 8) ? sb[lane] : 0.0f;
#pragma unroll
        for (int o = 4; o > 0; o >>= 1) {
            a += __shfl_down_sync(0xffu, a, o);
            b += __shfl_down_sync(0xffu, b, o);
        }
    }
}

__device__ __forceinline__ float block_rmax_256(float m) {
    __shared__ float sm[8];
    __syncthreads();   // protect sm reuse across successive reductions
    int lane = threadIdx.x & 31;
    int w = threadIdx.x >> 5;
#pragma unroll
    for (int o = 16; o > 0; o >>= 1)
        m = fmaxf(m, __shfl_down_sync(0xffffffffu, m, o));
    if (lane == 0) sm[w] = m;
    __syncthreads();
    if (w == 0) {
        m = (lane < 8) ? sm[lane] : 0.0f;
#pragma unroll
        for (int o = 4; o > 0; o >>= 1)
            m = fmaxf(m, __shfl_down_sync(0xffu, m, o));
    }
    return m;
}

// quantize y with scale sa: y = sa*(q1 + q2/254)
__device__ __forceinline__ void quant_store(float y, float inv, size_t i) {
    int q1 = __float2int_rn(y * inv);
    float r = fmaf(y, inv, -(float)q1);
    int q2 = __float2int_rn(r * QSCL2);
    g_aq1[i] = (int8_t)q1;
    g_aq2[i] = (int8_t)q2;
}

// ---------------------------------------------------------------------------
// Kernel 1: layernorm(x) over C, fused int8 2-level quantization.
// ---------------------------------------------------------------------------
__global__ __launch_bounds__(256) void k_ln_in(const float* __restrict__ x,
                                               const float* __restrict__ gam,
                                               const float* __restrict__ bet) {
    int t = blockIdx.x;
    int tid = threadIdx.x;
    const float* row = x + (size_t)t * CC;
    float v0 = row[tid], v1 = row[tid + 256], v2 = row[tid + 512];
    float s = v0 + v1 + v2;
    float sq = v0 * v0 + v1 * v1 + v2 * v2;
    block_reduce2_256(s, sq);
    __shared__ float s_mu, s_rstd;
    if (tid == 0) {
        float mu = s * (1.0f / CC);
        float var = sq * (1.0f / CC) - mu * mu;
        s_mu = mu;
        s_rstd = rsqrtf(var + 1e-5f);
    }
    __syncthreads();
    float mu = s_mu, rstd = s_rstd;
    float y0 = (v0 - mu) * rstd * gam[tid] + bet[tid];
    float y1 = (v1 - mu) * rstd * gam[tid + 256] + bet[tid + 256];
    float y2 = (v2 - mu) * rstd * gam[tid + 512] + bet[tid + 512];

    float m = fmaxf(fmaxf(fabsf(y0), fabsf(y1)), fabsf(y2));
    m = block_rmax_256(m);
    __shared__ float s_inv;
    if (tid == 0) {
        float sa = fmaxf(m, 1e-30f) * (1.0f / 127.0f);
        g_asc[t] = sa;
        s_inv = 1.0f / sa;
    }
    __syncthreads();
    float inv = s_inv;
    size_t base = (size_t)t * CC;
    quant_store(y0, inv, base + tid);
    quant_store(y1, inv, base + tid + 256);
    quant_store(y2, inv, base + tid + 512);
}

// ---------------------------------------------------------------------------
// Weight prep: per-output-column max (parallel over k), then quantized
// transpose. k_wmax: block per 32 columns, 256 thr = 8 k-slices x 32 cols.
// ---------------------------------------------------------------------------
__global__ __launch_bounds__(256) void k_wmax(const float* __restrict__ w,
                                              int N, float* __restrict__ bsc) {
    __shared__ float red[8][33];
    int tx = threadIdx.x & 31, ks = threadIdx.x >> 5;
    int n = blockIdx.x * 32 + tx;
    float m = 0.0f;
    for (int k = ks; k < CC; k += 8)
        m = fmaxf(m, fabsf(w[(size_t)k * N + n]));
    red[ks][tx] = m;
    __syncthreads();
    if (ks == 0) {
        float v = red[0][tx];
#pragma unroll
        for (int i = 1; i < 8; i++) v = fmaxf(v, red[i][tx]);
        bsc[n] = fmaxf(v, 1e-30f) * (1.0f / 127.0f);
    }
}

__global__ __launch_bounds__(256) void k_wquant(const float* __restrict__ w,
                                                int N, const float* __restrict__ bsc,
                                                int8_t* __restrict__ q1,
                                                int8_t* __restrict__ q2) {
    __shared__ float t[32][33];
    int n0 = blockIdx.x * 32, k0 = blockIdx.y * 32;
    int tx = threadIdx.x & 31, ty = threadIdx.x >> 5;
    for (int i = ty; i < 32; i += 8) t[i][tx] = w[(size_t)(k0 + i) * N + n0 + tx];
    __syncthreads();
    for (int i = ty; i < 32; i += 8) {
        float v = t[tx][i];  // element (k0+tx, n0+i)
        int n = n0 + i;
        float inv = 1.0f / bsc[n];
        int a = __float2int_rn(v * inv);
        float r = fmaf(v, inv, -(float)a);
        int b = __float2int_rn(r * QSCL2);
        size_t o = (size_t)n * CC + k0 + tx;
        q1[o] = (int8_t)a;
        q2[o] = (int8_t)b;
    }
}

// ---------------------------------------------------------------------------
// INT8 IMMA GEMM: C[M,NT] = sa[m]*sb[n]*(accH + accM/254)
// A = g_aq1/g_aq2 [M,768], B = q1/q2 [NT,768]. CTA 64x128, BK=64, 3 stages,
// 2 CTAs/SM. 8 warps 2(M) x 4(N); warp tile 32x32, two s32 acc sets.
// Rows padded to 80B -> conflict-free ldmatrix.
// ---------------------------------------------------------------------------
#define IBM 64
#define IBN 128
#define IBK 64
#define IPITCH 80
#define A_TILE (IBM * IPITCH)               // 5120
#define B_TILE (IBN * IPITCH)               // 10240
#define ISTAGE (2 * A_TILE + 2 * B_TILE)    // 30720
#define INSTG 3
#define IGSMEM (INSTG * ISTAGE)             // 92160 -> 2 CTAs/SM (184KB)

template <int ROWS>
__device__ __forceinline__ void load_i8_tile(uint32_t dst,
                                             const int8_t* __restrict__ g,
                                             int row0, int kc, int tid) {
#pragma unroll
    for (int i = 0; i < ROWS / 64; i++) {
        int idx = tid + i * 256;
        int r = idx >> 2, seg = idx & 3;
        cpa16(dst + (uint32_t)(r * IPITCH + seg * 16),
              g + (size_t)(row0 + r) * CC + kc + seg * 16);
    }
}

__device__ __forceinline__ void load_chunk_i8(uint32_t st, int bm, int bn, int kc,
                                              int tid, const int8_t* Bq1,
                                              const int8_t* Bq2) {
    load_i8_tile<64>(st,                       g_aq1, bm, kc, tid);
    load_i8_tile<64>(st + A_TILE,              g_aq2, bm, kc, tid);
    load_i8_tile<128>(st + 2 * A_TILE,         Bq1,   bn, kc, tid);
    load_i8_tile<128>(st + 2 * A_TILE + B_TILE, Bq2,  bn, kc, tid);
}

template <int LDC_>
__global__ __launch_bounds__(256, 2) void k_gemm_i8(const int8_t* __restrict__ Bq1,
                                                    const int8_t* __restrict__ Bq2,
                                                    const float* __restrict__ bsc,
                                                    float* __restrict__ C) {
    extern __shared__ char dsm[];
    uint32_t sb = smem_u32(dsm);
    int tid = threadIdx.x, lane = tid & 31, wid = tid >> 5;
    int wm = wid >> 2, wn = wid & 3;          // 2 x 4 warp grid
    int bm = blockIdx.y * IBM, bn = blockIdx.x * IBN;
    const int kt = CC / IBK;                  // 12

    uint32_t lrow = (uint32_t)(lane & 15);
    uint32_t lboff = (uint32_t)((lane >> 4) * 16);

    int accH[2][4][4], accM[2][4][4];
#pragma unroll
    for (int i = 0; i < 2; i++)
#pragma unroll
        for (int j = 0; j < 4; j++)
#pragma unroll
            for (int r = 0; r < 4; r++) { accH[i][j][r] = 0; accM[i][j][r] = 0; }

    // prologue: chunks 0,1 into stages 0,1
    load_chunk_i8(sb, bm, bn, 0, tid, Bq1, Bq2);
    asm volatile("cp.async.commit_group;" ::: "memory");
    load_chunk_i8(sb + ISTAGE, bm, bn, IBK, tid, Bq1, Bq2);
    asm volatile("cp.async.commit_group;" ::: "memory");

    for (int c = 0; c < kt; c++) {
        if (c + 1 < kt)
            asm volatile("cp.async.wait_group 1;" ::: "memory");
        else
            asm volatile("cp.async.wait_group 0;" ::: "memory");
        __syncthreads();   // chunk c visible; all warps past stage (c+2)%3

        if (c + 2 < kt) {
            load_chunk_i8(sb + ((c + 2) % INSTG) * ISTAGE, bm, bn, (c + 2) * IBK,
                          tid, Bq1, Bq2);
            asm volatile("cp.async.commit_group;" ::: "memory");
        }

        uint32_t st = sb + (c % INSTG) * ISTAGE;
#pragma unroll
        for (int ks = 0; ks < 2; ks++) {
            // B fragments: q1 and q2, 4 n-tiles of 8
            uint32_t b1f[4][2], b2f[4][2];
#pragma unroll
            for (int p = 0; p < 2; p++) {
                uint32_t addr = st + 2 * A_TILE +
                                (uint32_t)(wn * 32 + p * 16 + lrow) * IPITCH +
                                (uint32_t)(ks * 32) + lboff;
                uint32_t r[4];
                ldsm4(r, addr);
                b1f[2 * p][0] = r[0]; b1f[2 * p][1] = r[2];
                b1f[2 * p + 1][0] = r[1]; b1f[2 * p + 1][1] = r[3];
                ldsm4(r, addr + B_TILE);
                b2f[2 * p][0] = r[0]; b2f[2 * p][1] = r[2];
                b2f[2 * p + 1][0] = r[1]; b2f[2 * p + 1][1] = r[3];
            }
#pragma unroll
            for (int mt = 0; mt < 2; mt++) {
                uint32_t a1[4], a2[4];
                uint32_t aaddr = st +
                                 (uint32_t)(wm * 32 + mt * 16 + lrow) * IPITCH +
                                 (uint32_t)(ks * 32) + lboff;
                ldsm4(a1, aaddr);
                ldsm4(a2, aaddr + A_TILE);
#pragma unroll
                for (int nt = 0; nt < 4; nt++) mma_s8(accH[mt][nt], a1, b1f[nt]);
#pragma unroll
                for (int nt = 0; nt < 4; nt++) mma_s8(accM[mt][nt], a1, b2f[nt]);
#pragma unroll
                for (int nt = 0; nt < 4; nt++) mma_s8(accM[mt][nt], a2, b1f[nt]);
            }
        }
    }

    // epilogue: dequantize and store fp32
#pragma unroll
    for (int mt = 0; mt < 2; mt++) {
        int r0 = bm + wm * 32 + mt * 16 + (lane >> 2);
        float sa0 = g_asc[r0], sa1 = g_asc[r0 + 8];
#pragma unroll
        for (int nt = 0; nt < 4; nt++) {
            int cidx = bn + wn * 32 + nt * 8 + (lane & 3) * 2;
            float sb0 = bsc[cidx], sb1 = bsc[cidx + 1];
            const int* h = accH[mt][nt];
            const int* m = accM[mt][nt];
            float v00 = sa0 * sb0 * ((float)h[0] + (float)m[0] * (1.0f / QSCL2));
            float v01 = sa0 * sb1 * ((float)h[1] + (float)m[1] * (1.0f / QSCL2));
            float v10 = sa1 * sb0 * ((float)h[2] + (float)m[2] * (1.0f / QSCL2));
            float v11 = sa1 * sb1 * ((float)h[3] + (float)m[3] * (1.0f / QSCL2));
            *(float2*)(C + (size_t)r0 * LDC_ + cidx) = make_float2(v00, v01);
            *(float2*)(C + (size_t)(r0 + 8) * LDC_ + cidx) = make_float2(v10, v11);
        }
    }
}

// ---------------------------------------------------------------------------
// per-token inverse L2 norm of k only (qinv computed inside k_attn_ln).
// ---------------------------------------------------------------------------
__global__ __launch_bounds__(256) void k_norms() {
    int t = blockIdx.x;
    int tid = threadIdx.x;
    const float* krow = g_qkv + (size_t)t * QKVD + EE;
    float k0 = krow[tid], k1 = krow[tid + 256], k2 = krow[tid + 512];
    float sk = k0 * k0 + k1 * k1 + k2 * k2;
    float dummy = 0.0f;
    block_reduce2_256(sk, dummy);
    if (tid == 0) g_kinv[t] = 1.0f / fmaxf(sqrtf(sk), 1e-12f);
}

// ---------------------------------------------------------------------------
// kv partial sums: kv[b,e] = sum_t phi_k[t,e] * v[t,e]
// ---------------------------------------------------------------------------
__global__ __launch_bounds__(256) void k_kvred() {
    int b = blockIdx.y;
    int chunk = blockIdx.x;
    int tid = threadIdx.x;
    float a0 = 0.f, a1 = 0.f, a2 = 0.f;
    int t0 = b * NN + chunk * 128;
    for (int i = 0; i < 128; i++) {
        const float* row = g_qkv + (size_t)(t0 + i) * QKVD;
        const float* kr = row + EE;
        const float* vr = row + 2 * EE;
        float ki = g_kinv[t0 + i];
        a0 += (kr[tid] * ki) * vr[tid];
        a1 += (kr[tid + 256] * ki) * vr[tid + 256];
        a2 += (kr[tid + 512] * ki) * vr[tid + 512];
    }
    float* dst = g_kvpart + ((size_t)chunk * BQ + b) * EE;
    dst[tid] = a0; dst[tid + 256] = a1; dst[tid + 512] = a2;
}

__global__ __launch_bounds__(256) void k_kvsum() {
    int i = blockIdx.x * 256 + threadIdx.x;
    float s = 0.f;
#pragma unroll
    for (int c = 0; c < 32; c++) s += g_kvpart[(size_t)c * BQ * EE + i];
    g_kv[i] = s;
}

// ---------------------------------------------------------------------------
// qinv inline; attn = phi_q*kv; layernorm over E; fused int8 quantization.
// ---------------------------------------------------------------------------
__global__ __launch_bounds__(256) void k_attn_ln(const float* __restrict__ gam,
                                                 const float* __restrict__ bet) {
    int t = blockIdx.x;
    int b = t >> 12;
    int tid = threadIdx.x;
    const float* qrow = g_qkv + (size_t)t * QKVD;
    const float* kvb = g_kv + b * EE;
    float q0 = qrow[tid], q1 = qrow[tid + 256], q2 = qrow[tid + 512];

    float qsq = q0 * q0 + q1 * q1 + q2 * q2;
    float dummy = 0.0f;
    block_reduce2_256(qsq, dummy);
    __shared__ float s_qi;
    if (tid == 0) s_qi = 1.0f / fmaxf(sqrtf(qsq), 1e-12f);
    __syncthreads();
    float qi = s_qi;

    float a0 = (q0 * qi) * kvb[tid];
    float a1 = (q1 * qi) * kvb[tid + 256];
    float a2 = (q2 * qi) * kvb[tid + 512];
    float s = a0 + a1 + a2;
    float sq = a0 * a0 + a1 * a1 + a2 * a2;
    block_reduce2_256(s, sq);
    __shared__ float s_mu, s_rstd;
    if (tid == 0) {
        float mu = s * (1.0f / EE);
        float var = sq * (1.0f / EE) - mu * mu;
        s_mu = mu;
        s_rstd = rsqrtf(var + 1e-5f);
    }
    __syncthreads();
    float mu = s_mu, rstd = s_rstd;
    float y0 = (a0 - mu) * rstd * gam[tid] + bet[tid];
    float y1 = (a1 - mu) * rstd * gam[tid + 256] + bet[tid + 256];
    float y2 = (a2 - mu) * rstd * gam[tid + 512] + bet[tid + 512];

    float m = fmaxf(fmaxf(fabsf(y0), fabsf(y1)), fabsf(y2));
    m = block_rmax_256(m);
    __shared__ float s_inv;
    if (tid == 0) {
        float sa = fmaxf(m, 1e-30f) * (1.0f / 127.0f);
        g_asc[t] = sa;
        s_inv = 1.0f / sa;
    }
    __syncthreads();
    float inv = s_inv;
    size_t base = (size_t)t * EE;
    quant_store(y0, inv, base + tid);
    quant_store(y1, inv, base + tid + 256);
    quant_store(y2, inv, base + tid + 512);
}

// ---------------------------------------------------------------------------
extern "C" void kernel_launch(void* const* d_in, const int* in_sizes, int n_in,
                              void* d_out, int out_size) {
    const float* x        = (const float*)d_in[0];
    const float* w_qkv    = (const float*)d_in[1];
    const float* w_proj   = (const float*)d_in[2];
    const float* ln_in_g  = (const float*)d_in[3];
    const float* ln_in_b  = (const float*)d_in[4];
    const float* ln_out_g = (const float*)d_in[5];
    const float* ln_out_b = (const float*)d_in[6];
    float* out = (float*)d_out;

    cudaFuncSetAttribute(k_gemm_i8<QKVD>, cudaFuncAttributeMaxDynamicSharedMemorySize, IGSMEM);
    cudaFuncSetAttribute(k_gemm_i8<CC>, cudaFuncAttributeMaxDynamicSharedMemorySize, IGSMEM);

    int8_t* bq1q; cudaGetSymbolAddress((void**)&bq1q, g_bq1q);
    int8_t* bq2q; cudaGetSymbolAddress((void**)&bq2q, g_bq2q);
    float*  bscq; cudaGetSymbolAddress((void**)&bscq, g_bscq);
    int8_t* bq1p; cudaGetSymbolAddress((void**)&bq1p, g_bq1p);
    int8_t* bq2p; cudaGetSymbolAddress((void**)&bq2p, g_bq2p);
    float*  bscp; cudaGetSymbolAddress((void**)&bscp, g_bscp);
    float*  qkv;  cudaGetSymbolAddress((void**)&qkv, g_qkv);

    k_ln_in<<<MM, 256>>>(x, ln_in_g, ln_in_b);
    k_wmax<<<QKVD / 32, 256>>>(w_qkv, QKVD, bscq);
    k_wquant<<<dim3(QKVD / 32, CC / 32), 256>>>(w_qkv, QKVD, bscq, bq1q, bq2q);
    k_wmax<<<CC / 32, 256>>>(w_proj, CC, bscp);
    k_wquant<<<dim3(CC / 32, CC / 32), 256>>>(w_proj, CC, bscp, bq1p, bq2p);
    k_gemm_i8<QKVD><<<dim3(QKVD / IBN, MM / IBM), 256, IGSMEM>>>(bq1q, bq2q, bscq, qkv);
    k_norms<<<MM, 256>>>();
    k_kvred<<<dim3(32, BQ), 256>>>();
    k_kvsum<<<BQ * EE / 256, 256>>>();
    k_attn_ln<<<MM, 256>>>(ln_out_g, ln_out_b);
    k_gemm_i8<CC><<<dim3(CC / IBN, MM / IBM), 256, IGSMEM>>>(bq1p, bq2p, bscp, out);
}

// round 12
// speedup vs baseline: 3.2356x; 1.0947x over previous
#include <cuda_runtime.h>
#include <cuda_bf16.h>
#include <cstdint>

// Problem constants
#define BQ 8
#define NN 4096
#define CC 768
#define EE 768
#define MM (BQ * NN)     // 32768 tokens
#define QKVD (3 * EE)    // 2304

// ---------------- device scratch (no allocation allowed) -------------------
__device__ __align__(128) float  g_qkv[(size_t)MM * QKVD];    // GEMM1 out fp32
__device__ __align__(128) int8_t g_aq1[(size_t)MM * CC];      // A quant level 1
__device__ __align__(128) int8_t g_aq2[(size_t)MM * CC];      // A quant level 2
__device__ __align__(128) float  g_asc[MM];                   // A row scales
__device__ __align__(128) int8_t g_bq1q[(size_t)QKVD * CC];   // w_qkv^T q1 [2304,768]
__device__ __align__(128) int8_t g_bq2q[(size_t)QKVD * CC];
__device__ __align__(128) float  g_bscq[QKVD];
__device__ __align__(128) int8_t g_bq1p[(size_t)EE * CC];     // w_proj^T q1 [768,768]
__device__ __align__(128) int8_t g_bq2p[(size_t)EE * CC];
__device__ __align__(128) float  g_bscp[EE];
__device__ float g_kvpart[32 * BQ * EE];
__device__ float g_kv[BQ * EE];
__device__ float g_kinv[MM];

#define QSCL2 254.0f

// ---------------------------- helpers --------------------------------------
__device__ __forceinline__ uint32_t smem_u32(const void* p) {
    uint32_t a;
    asm("{ .reg .u64 t; cvta.to.shared.u64 t, %1; cvt.u32.u64 %0, t; }"
        : "=r"(a) : "l"(p));
    return a;
}
__device__ __forceinline__ void cpa16(uint32_t dst, const void* src) {
    asm volatile("cp.async.cg.shared.global [%0], [%1], 16;" :: "r"(dst), "l"(src));
}
__device__ __forceinline__ void ldsm4(uint32_t* r, uint32_t addr) {
    asm volatile("ldmatrix.sync.aligned.m8n8.x4.shared.b16 {%0,%1,%2,%3}, [%4];"
                 : "=r"(r[0]), "=r"(r[1]), "=r"(r[2]), "=r"(r[3]) : "r"(addr));
}
__device__ __forceinline__ void mma_s8(int* d, const uint32_t* a,
                                       const uint32_t* b) {
    asm volatile(
        "mma.sync.aligned.m16n8k32.row.col.s32.s8.s8.s32 "
        "{%0,%1,%2,%3},{%4,%5,%6,%7},{%8,%9},{%0,%1,%2,%3};"
        : "+r"(d[0]), "+r"(d[1]), "+r"(d[2]), "+r"(d[3])
        : "r"(a[0]), "r"(a[1]), "r"(a[2]), "r"(a[3]), "r"(b[0]), "r"(b[1]));
}

// warp butterfly reductions: every lane gets the result; no barriers
__device__ __forceinline__ float warp_sum(float v) {
#pragma unroll
    for (int o = 16; o > 0; o >>= 1) v += __shfl_xor_sync(0xffffffffu, v, o);
    return v;
}
__device__ __forceinline__ float warp_max(float v) {
#pragma unroll
    for (int o = 16; o > 0; o >>= 1)
        v = fmaxf(v, __shfl_xor_sync(0xffffffffu, v, o));
    return v;
}

// block reduce (only used by kvred path kernels that keep block-per-token)
__device__ __forceinline__ void block_reduce2_256(float& a, float& b) {
    __shared__ float sa[8], sb[8];
    int lane = threadIdx.x & 31;
    int w = threadIdx.x >> 5;
#pragma unroll
    for (int o = 16; o > 0; o >>= 1) {
        a += __shfl_down_sync(0xffffffffu, a, o);
        b += __shfl_down_sync(0xffffffffu, b, o);
    }
    if (lane == 0) { sa[w] = a; sb[w] = b; }
    __syncthreads();
    if (w == 0) {
        a = (lane < 8) ? sa[lane] : 0.0f;
        b = (lane < 8) ? sb[lane] : 0.0f;
#pragma unroll
        for (int o = 4; o > 0; o >>= 1) {
            a += __shfl_down_sync(0xffu, a, o);
            b += __shfl_down_sync(0xffu, b, o);
        }
    }
}

// quantize 4 values -> two char4 (levels 1 and 2)
__device__ __forceinline__ void quant4(const float* y, float inv,
                                       char4& c1, char4& c2) {
    int q1[4], q2[4];
#pragma unroll
    for (int e = 0; e < 4; e++) {
        q1[e] = __float2int_rn(y[e] * inv);
        float r = fmaf(y[e], inv, -(float)q1[e]);
        q2[e] = __float2int_rn(r * QSCL2);
    }
    c1 = make_char4((char)q1[0], (char)q1[1], (char)q1[2], (char)q1[3]);
    c2 = make_char4((char)q2[0], (char)q2[1], (char)q2[2], (char)q2[3]);
}

// ---------------------------------------------------------------------------
// Kernel 1: warp-per-token layernorm(x) + int8 2-level quant. No barriers.
// ---------------------------------------------------------------------------
__global__ __launch_bounds__(256) void k_ln_in(const float* __restrict__ x,
                                               const float* __restrict__ gam,
                                               const float* __restrict__ bet) {
    int lane = threadIdx.x & 31;
    int t = blockIdx.x * 8 + (threadIdx.x >> 5);
    const float4* row = (const float4*)(x + (size_t)t * CC);
    const float4* g4 = (const float4*)gam;
    const float4* b4 = (const float4*)bet;

    float4 v[6];
    float s = 0.f, sq = 0.f;
#pragma unroll
    for (int g = 0; g < 6; g++) {
        v[g] = row[lane + 32 * g];
        s += v[g].x + v[g].y + v[g].z + v[g].w;
        sq += v[g].x * v[g].x + v[g].y * v[g].y + v[g].z * v[g].z + v[g].w * v[g].w;
    }
    s = warp_sum(s);
    sq = warp_sum(sq);
    float mu = s * (1.0f / CC);
    float rstd = rsqrtf(sq * (1.0f / CC) - mu * mu + 1e-5f);

    float y[6][4];
    float m = 0.f;
#pragma unroll
    for (int g = 0; g < 6; g++) {
        float4 gg = g4[lane + 32 * g], bb = b4[lane + 32 * g];
        y[g][0] = (v[g].x - mu) * rstd * gg.x + bb.x;
        y[g][1] = (v[g].y - mu) * rstd * gg.y + bb.y;
        y[g][2] = (v[g].z - mu) * rstd * gg.z + bb.z;
        y[g][3] = (v[g].w - mu) * rstd * gg.w + bb.w;
#pragma unroll
        for (int e = 0; e < 4; e++) m = fmaxf(m, fabsf(y[g][e]));
    }
    m = warp_max(m);
    float sa = fmaxf(m, 1e-30f) * (1.0f / 127.0f);
    float inv = 1.0f / sa;
    if (lane == 0) g_asc[t] = sa;

    char4* d1 = (char4*)(g_aq1 + (size_t)t * CC);
    char4* d2 = (char4*)(g_aq2 + (size_t)t * CC);
#pragma unroll
    for (int g = 0; g < 6; g++) {
        char4 c1, c2;
        quant4(y[g], inv, c1, c2);
        d1[lane + 32 * g] = c1;
        d2[lane + 32 * g] = c2;
    }
}

// ---------------------------------------------------------------------------
// Weight prep: per-output-column max (parallel over k), then quantized
// transpose.
// ---------------------------------------------------------------------------
__global__ __launch_bounds__(256) void k_wmax(const float* __restrict__ w,
                                              int N, float* __restrict__ bsc) {
    __shared__ float red[8][33];
    int tx = threadIdx.x & 31, ks = threadIdx.x >> 5;
    int n = blockIdx.x * 32 + tx;
    float m = 0.0f;
    for (int k = ks; k < CC; k += 8)
        m = fmaxf(m, fabsf(w[(size_t)k * N + n]));
    red[ks][tx] = m;
    __syncthreads();
    if (ks == 0) {
        float v = red[0][tx];
#pragma unroll
        for (int i = 1; i < 8; i++) v = fmaxf(v, red[i][tx]);
        bsc[n] = fmaxf(v, 1e-30f) * (1.0f / 127.0f);
    }
}

__global__ __launch_bounds__(256) void k_wquant(const float* __restrict__ w,
                                                int N, const float* __restrict__ bsc,
                                                int8_t* __restrict__ q1,
                                                int8_t* __restrict__ q2) {
    __shared__ float t[32][33];
    int n0 = blockIdx.x * 32, k0 = blockIdx.y * 32;
    int tx = threadIdx.x & 31, ty = threadIdx.x >> 5;
    for (int i = ty; i < 32; i += 8) t[i][tx] = w[(size_t)(k0 + i) * N + n0 + tx];
    __syncthreads();
    for (int i = ty; i < 32; i += 8) {
        float v = t[tx][i];  // element (k0+tx, n0+i)
        int n = n0 + i;
        float inv = 1.0f / bsc[n];
        int a = __float2int_rn(v * inv);
        float r = fmaf(v, inv, -(float)a);
        int b = __float2int_rn(r * QSCL2);
        size_t o = (size_t)n * CC + k0 + tx;
        q1[o] = (int8_t)a;
        q2[o] = (int8_t)b;
    }
}

// ---------------------------------------------------------------------------
// INT8 IMMA GEMM: C[M,NT] = sa[m]*sb[n]*(accH + accM/254)
// CTA 64x128, BK=64, 3 stages, 2 CTAs/SM. 8 warps 2(M) x 4(N).
// ---------------------------------------------------------------------------
#define IBM 64
#define IBN 128
#define IBK 64
#define IPITCH 80
#define A_TILE (IBM * IPITCH)               // 5120
#define B_TILE (IBN * IPITCH)               // 10240
#define ISTAGE (2 * A_TILE + 2 * B_TILE)    // 30720
#define INSTG 3
#define IGSMEM (INSTG * ISTAGE)             // 92160 -> 2 CTAs/SM

template <int ROWS>
__device__ __forceinline__ void load_i8_tile(uint32_t dst,
                                             const int8_t* __restrict__ g,
                                             int row0, int kc, int tid) {
#pragma unroll
    for (int i = 0; i < ROWS / 64; i++) {
        int idx = tid + i * 256;
        int r = idx >> 2, seg = idx & 3;
        cpa16(dst + (uint32_t)(r * IPITCH + seg * 16),
              g + (size_t)(row0 + r) * CC + kc + seg * 16);
    }
}

__device__ __forceinline__ void load_chunk_i8(uint32_t st, int bm, int bn, int kc,
                                              int tid, const int8_t* Bq1,
                                              const int8_t* Bq2) {
    load_i8_tile<64>(st,                       g_aq1, bm, kc, tid);
    load_i8_tile<64>(st + A_TILE,              g_aq2, bm, kc, tid);
    load_i8_tile<128>(st + 2 * A_TILE,         Bq1,   bn, kc, tid);
    load_i8_tile<128>(st + 2 * A_TILE + B_TILE, Bq2,  bn, kc, tid);
}

template <int LDC_>
__global__ __launch_bounds__(256, 2) void k_gemm_i8(const int8_t* __restrict__ Bq1,
                                                    const int8_t* __restrict__ Bq2,
                                                    const float* __restrict__ bsc,
                                                    float* __restrict__ C) {
    extern __shared__ char dsm[];
    uint32_t sb = smem_u32(dsm);
    int tid = threadIdx.x, lane = tid & 31, wid = tid >> 5;
    int wm = wid >> 2, wn = wid & 3;          // 2 x 4 warp grid
    int bm = blockIdx.y * IBM, bn = blockIdx.x * IBN;
    const int kt = CC / IBK;                  // 12

    uint32_t lrow = (uint32_t)(lane & 15);
    uint32_t lboff = (uint32_t)((lane >> 4) * 16);

    int accH[2][4][4], accM[2][4][4];
#pragma unroll
    for (int i = 0; i < 2; i++)
#pragma unroll
        for (int j = 0; j < 4; j++)
#pragma unroll
            for (int r = 0; r < 4; r++) { accH[i][j][r] = 0; accM[i][j][r] = 0; }

    // prologue: chunks 0,1 into stages 0,1
    load_chunk_i8(sb, bm, bn, 0, tid, Bq1, Bq2);
    asm volatile("cp.async.commit_group;" ::: "memory");
    load_chunk_i8(sb + ISTAGE, bm, bn, IBK, tid, Bq1, Bq2);
    asm volatile("cp.async.commit_group;" ::: "memory");

    for (int c = 0; c < kt; c++) {
        if (c + 1 < kt)
            asm volatile("cp.async.wait_group 1;" ::: "memory");
        else
            asm volatile("cp.async.wait_group 0;" ::: "memory");
        __syncthreads();   // chunk c visible; all warps past stage (c+2)%3

        if (c + 2 < kt) {
            load_chunk_i8(sb + ((c + 2) % INSTG) * ISTAGE, bm, bn, (c + 2) * IBK,
                          tid, Bq1, Bq2);
            asm volatile("cp.async.commit_group;" ::: "memory");
        }

        uint32_t st = sb + (c % INSTG) * ISTAGE;
#pragma unroll
        for (int ks = 0; ks < 2; ks++) {
            uint32_t b1f[4][2], b2f[4][2];
#pragma unroll
            for (int p = 0; p < 2; p++) {
                uint32_t addr = st + 2 * A_TILE +
                                (uint32_t)(wn * 32 + p * 16 + lrow) * IPITCH +
                                (uint32_t)(ks * 32) + lboff;
                uint32_t r[4];
                ldsm4(r, addr);
                b1f[2 * p][0] = r[0]; b1f[2 * p][1] = r[2];
                b1f[2 * p + 1][0] = r[1]; b1f[2 * p + 1][1] = r[3];
                ldsm4(r, addr + B_TILE);
                b2f[2 * p][0] = r[0]; b2f[2 * p][1] = r[2];
                b2f[2 * p + 1][0] = r[1]; b2f[2 * p + 1][1] = r[3];
            }
#pragma unroll
            for (int mt = 0; mt < 2; mt++) {
                uint32_t a1[4], a2[4];
                uint32_t aaddr = st +
                                 (uint32_t)(wm * 32 + mt * 16 + lrow) * IPITCH +
                                 (uint32_t)(ks * 32) + lboff;
                ldsm4(a1, aaddr);
                ldsm4(a2, aaddr + A_TILE);
#pragma unroll
                for (int nt = 0; nt < 4; nt++) mma_s8(accH[mt][nt], a1, b1f[nt]);
#pragma unroll
                for (int nt = 0; nt < 4; nt++) mma_s8(accM[mt][nt], a1, b2f[nt]);
#pragma unroll
                for (int nt = 0; nt < 4; nt++) mma_s8(accM[mt][nt], a2, b1f[nt]);
            }
        }
    }

    // epilogue: dequantize and store fp32
#pragma unroll
    for (int mt = 0; mt < 2; mt++) {
        int r0 = bm + wm * 32 + mt * 16 + (lane >> 2);
        float sa0 = g_asc[r0], sa1 = g_asc[r0 + 8];
#pragma unroll
        for (int nt = 0; nt < 4; nt++) {
            int cidx = bn + wn * 32 + nt * 8 + (lane & 3) * 2;
            float sb0 = bsc[cidx], sb1 = bsc[cidx + 1];
            const int* h = accH[mt][nt];
            const int* m = accM[mt][nt];
            float v00 = sa0 * sb0 * ((float)h[0] + (float)m[0] * (1.0f / QSCL2));
            float v01 = sa0 * sb1 * ((float)h[1] + (float)m[1] * (1.0f / QSCL2));
            float v10 = sa1 * sb0 * ((float)h[2] + (float)m[2] * (1.0f / QSCL2));
            float v11 = sa1 * sb1 * ((float)h[3] + (float)m[3] * (1.0f / QSCL2));
            *(float2*)(C + (size_t)r0 * LDC_ + cidx) = make_float2(v00, v01);
            *(float2*)(C + (size_t)(r0 + 8) * LDC_ + cidx) = make_float2(v10, v11);
        }
    }
}

// ---------------------------------------------------------------------------
// warp-per-token inverse L2 norm of k. No barriers.
// ---------------------------------------------------------------------------
__global__ __launch_bounds__(256) void k_norms() {
    int lane = threadIdx.x & 31;
    int t = blockIdx.x * 8 + (threadIdx.x >> 5);
    const float4* krow = (const float4*)(g_qkv + (size_t)t * QKVD + EE);
    float sk = 0.f;
#pragma unroll
    for (int g = 0; g < 6; g++) {
        float4 k = krow[lane + 32 * g];
        sk += k.x * k.x + k.y * k.y + k.z * k.z + k.w * k.w;
    }
    sk = warp_sum(sk);
    if (lane == 0) g_kinv[t] = 1.0f / fmaxf(sqrtf(sk), 1e-12f);
}

// ---------------------------------------------------------------------------
// kv partial sums: kv[b,e] = sum_t phi_k[t,e] * v[t,e]
// ---------------------------------------------------------------------------
__global__ __launch_bounds__(256) void k_kvred() {
    int b = blockIdx.y;
    int chunk = blockIdx.x;
    int tid = threadIdx.x;
    float a0 = 0.f, a1 = 0.f, a2 = 0.f;
    int t0 = b * NN + chunk * 128;
    for (int i = 0; i < 128; i++) {
        const float* row = g_qkv + (size_t)(t0 + i) * QKVD;
        const float* kr = row + EE;
        const float* vr = row + 2 * EE;
        float ki = g_kinv[t0 + i];
        a0 += (kr[tid] * ki) * vr[tid];
        a1 += (kr[tid + 256] * ki) * vr[tid + 256];
        a2 += (kr[tid + 512] * ki) * vr[tid + 512];
    }
    float* dst = g_kvpart + ((size_t)chunk * BQ + b) * EE;
    dst[tid] = a0; dst[tid + 256] = a1; dst[tid + 512] = a2;
}

__global__ __launch_bounds__(256) void k_kvsum() {
    int i = blockIdx.x * 256 + threadIdx.x;
    float s = 0.f;
#pragma unroll
    for (int c = 0; c < 32; c++) s += g_kvpart[(size_t)c * BQ * EE + i];
    g_kv[i] = s;
}

// ---------------------------------------------------------------------------
// warp-per-token: qinv, attn = phi_q*kv, layernorm, int8 quant. No barriers.
// ---------------------------------------------------------------------------
__global__ __launch_bounds__(256) void k_attn_ln(const float* __restrict__ gam,
                                                 const float* __restrict__ bet) {
    int lane = threadIdx.x & 31;
    int t = blockIdx.x * 8 + (threadIdx.x >> 5);
    int b = t >> 12;
    const float4* qrow = (const float4*)(g_qkv + (size_t)t * QKVD);
    const float4* kvb = (const float4*)(g_kv + b * EE);
    const float4* g4 = (const float4*)gam;
    const float4* b4 = (const float4*)bet;

    float4 q[6];
    float qsq = 0.f;
#pragma unroll
    for (int g = 0; g < 6; g++) {
        q[g] = qrow[lane + 32 * g];
        qsq += q[g].x * q[g].x + q[g].y * q[g].y + q[g].z * q[g].z + q[g].w * q[g].w;
    }
    qsq = warp_sum(qsq);
    float qi = 1.0f / fmaxf(sqrtf(qsq), 1e-12f);

    float a[6][4];
    float s = 0.f, sq = 0.f;
#pragma unroll
    for (int g = 0; g < 6; g++) {
        float4 kv = kvb[lane + 32 * g];
        a[g][0] = (q[g].x * qi) * kv.x;
        a[g][1] = (q[g].y * qi) * kv.y;
        a[g][2] = (q[g].z * qi) * kv.z;
        a[g][3] = (q[g].w * qi) * kv.w;
#pragma unroll
        for (int e = 0; e < 4; e++) { s += a[g][e]; sq += a[g][e] * a[g][e]; }
    }
    s = warp_sum(s);
    sq = warp_sum(sq);
    float mu = s * (1.0f / EE);
    float rstd = rsqrtf(sq * (1.0f / EE) - mu * mu + 1e-5f);

    float y[6][4];
    float m = 0.f;
#pragma unroll
    for (int g = 0; g < 6; g++) {
        float4 gg = g4[lane + 32 * g], bb = b4[lane + 32 * g];
        y[g][0] = (a[g][0] - mu) * rstd * gg.x + bb.x;
        y[g][1] = (a[g][1] - mu) * rstd * gg.y + bb.y;
        y[g][2] = (a[g][2] - mu) * rstd * gg.z + bb.z;
        y[g][3] = (a[g][3] - mu) * rstd * gg.w + bb.w;
#pragma unroll
        for (int e = 0; e < 4; e++) m = fmaxf(m, fabsf(y[g][e]));
    }
    m = warp_max(m);
    float sa = fmaxf(m, 1e-30f) * (1.0f / 127.0f);
    float inv = 1.0f / sa;
    if (lane == 0) g_asc[t] = sa;

    char4* d1 = (char4*)(g_aq1 + (size_t)t * EE);
    char4* d2 = (char4*)(g_aq2 + (size_t)t * EE);
#pragma unroll
    for (int g = 0; g < 6; g++) {
        char4 c1, c2;
        quant4(y[g], inv, c1, c2);
        d1[lane + 32 * g] = c1;
        d2[lane + 32 * g] = c2;
    }
}

// ---------------------------------------------------------------------------
extern "C" void kernel_launch(void* const* d_in, const int* in_sizes, int n_in,
                              void* d_out, int out_size) {
    const float* x        = (const float*)d_in[0];
    const float* w_qkv    = (const float*)d_in[1];
    const float* w_proj   = (const float*)d_in[2];
    const float* ln_in_g  = (const float*)d_in[3];
    const float* ln_in_b  = (const float*)d_in[4];
    const float* ln_out_g = (const float*)d_in[5];
    const float* ln_out_b = (const float*)d_in[6];
    float* out = (float*)d_out;

    cudaFuncSetAttribute(k_gemm_i8<QKVD>, cudaFuncAttributeMaxDynamicSharedMemorySize, IGSMEM);
    cudaFuncSetAttribute(k_gemm_i8<CC>, cudaFuncAttributeMaxDynamicSharedMemorySize, IGSMEM);

    int8_t* bq1q; cudaGetSymbolAddress((void**)&bq1q, g_bq1q);
    int8_t* bq2q; cudaGetSymbolAddress((void**)&bq2q, g_bq2q);
    float*  bscq; cudaGetSymbolAddress((void**)&bscq, g_bscq);
    int8_t* bq1p; cudaGetSymbolAddress((void**)&bq1p, g_bq1p);
    int8_t* bq2p; cudaGetSymbolAddress((void**)&bq2p, g_bq2p);
    float*  bscp; cudaGetSymbolAddress((void**)&bscp, g_bscp);
    float*  qkv;  cudaGetSymbolAddress((void**)&qkv, g_qkv);

    k_ln_in<<<MM / 8, 256>>>(x, ln_in_g, ln_in_b);
    k_wmax<<<QKVD / 32, 256>>>(w_qkv, QKVD, bscq);
    k_wquant<<<dim3(QKVD / 32, CC / 32), 256>>>(w_qkv, QKVD, bscq, bq1q, bq2q);
    k_wmax<<<CC / 32, 256>>>(w_proj, CC, bscp);
    k_wquant<<<dim3(CC / 32, CC / 32), 256>>>(w_proj, CC, bscp, bq1p, bq2p);
    k_gemm_i8<QKVD><<<dim3(QKVD / IBN, MM / IBM), 256, IGSMEM>>>(bq1q, bq2q, bscq, qkv);
    k_norms<<<MM / 8, 256>>>();
    k_kvred<<<dim3(32, BQ), 256>>>();
    k_kvsum<<<BQ * EE / 256, 256>>>();
    k_attn_ln<<<MM / 8, 256>>>(ln_out_g, ln_out_b);
    k_gemm_i8<CC><<<dim3(CC / IBN, MM / IBM), 256, IGSMEM>>>(bq1p, bq2p, bscp, out);
}

// round 13
// speedup vs baseline: 3.2901x; 1.0168x over previous
#include <cuda_runtime.h>
#include <cuda_bf16.h>
#include <cstdint>

// Problem constants
#define BQ 8
#define NN 4096
#define CC 768
#define EE 768
#define MM (BQ * NN)     // 32768 tokens
#define QKVD (3 * EE)    // 2304
#define KVCH 64          // kv reduction chunks per batch

// ---------------- device scratch (no allocation allowed) -------------------
__device__ __align__(128) float  g_qkv[(size_t)MM * QKVD];    // GEMM1 out fp32
__device__ __align__(128) int8_t g_aq1[(size_t)MM * CC];      // A quant level 1
__device__ __align__(128) int8_t g_aq2[(size_t)MM * CC];      // A quant level 2
__device__ __align__(128) float  g_asc[MM];                   // A row scales
__device__ __align__(128) int8_t g_bq1q[(size_t)QKVD * CC];   // w_qkv^T q1 [2304,768]
__device__ __align__(128) int8_t g_bq2q[(size_t)QKVD * CC];
__device__ __align__(128) float  g_bscq[QKVD];
__device__ __align__(128) int8_t g_bq1p[(size_t)EE * CC];     // w_proj^T q1 [768,768]
__device__ __align__(128) int8_t g_bq2p[(size_t)EE * CC];
__device__ __align__(128) float  g_bscp[EE];
__device__ float g_kvpart[KVCH * BQ * EE];
__device__ float g_kv[BQ * EE];
__device__ float g_kinv[MM];

#define QSCL2 254.0f

// ---------------------------- helpers --------------------------------------
__device__ __forceinline__ uint32_t smem_u32(const void* p) {
    uint32_t a;
    asm("{ .reg .u64 t; cvta.to.shared.u64 t, %1; cvt.u32.u64 %0, t; }"
        : "=r"(a) : "l"(p));
    return a;
}
__device__ __forceinline__ void cpa16(uint32_t dst, const void* src) {
    asm volatile("cp.async.cg.shared.global [%0], [%1], 16;" :: "r"(dst), "l"(src));
}
__device__ __forceinline__ void ldsm4(uint32_t* r, uint32_t addr) {
    asm volatile("ldmatrix.sync.aligned.m8n8.x4.shared.b16 {%0,%1,%2,%3}, [%4];"
                 : "=r"(r[0]), "=r"(r[1]), "=r"(r[2]), "=r"(r[3]) : "r"(addr));
}
__device__ __forceinline__ void mma_s8(int* d, const uint32_t* a,
                                       const uint32_t* b) {
    asm volatile(
        "mma.sync.aligned.m16n8k32.row.col.s32.s8.s8.s32 "
        "{%0,%1,%2,%3},{%4,%5,%6,%7},{%8,%9},{%0,%1,%2,%3};"
        : "+r"(d[0]), "+r"(d[1]), "+r"(d[2]), "+r"(d[3])
        : "r"(a[0]), "r"(a[1]), "r"(a[2]), "r"(a[3]), "r"(b[0]), "r"(b[1]));
}

// warp butterfly reductions: every lane gets the result; no barriers
__device__ __forceinline__ float warp_sum(float v) {
#pragma unroll
    for (int o = 16; o > 0; o >>= 1) v += __shfl_xor_sync(0xffffffffu, v, o);
    return v;
}
__device__ __forceinline__ float warp_max(float v) {
#pragma unroll
    for (int o = 16; o > 0; o >>= 1)
        v = fmaxf(v, __shfl_xor_sync(0xffffffffu, v, o));
    return v;
}

// quantize 4 values -> two char4 (levels 1 and 2)
__device__ __forceinline__ void quant4(const float* y, float inv,
                                       char4& c1, char4& c2) {
    int q1[4], q2[4];
#pragma unroll
    for (int e = 0; e < 4; e++) {
        q1[e] = __float2int_rn(y[e] * inv);
        float r = fmaf(y[e], inv, -(float)q1[e]);
        q2[e] = __float2int_rn(r * QSCL2);
    }
    c1 = make_char4((char)q1[0], (char)q1[1], (char)q1[2], (char)q1[3]);
    c2 = make_char4((char)q2[0], (char)q2[1], (char)q2[2], (char)q2[3]);
}

// ---------------------------------------------------------------------------
// Kernel 1: warp-per-token layernorm(x) + int8 2-level quant. No barriers.
// ---------------------------------------------------------------------------
__global__ __launch_bounds__(256) void k_ln_in(const float* __restrict__ x,
                                               const float* __restrict__ gam,
                                               const float* __restrict__ bet) {
    int lane = threadIdx.x & 31;
    int t = blockIdx.x * 8 + (threadIdx.x >> 5);
    const float4* row = (const float4*)(x + (size_t)t * CC);
    const float4* g4 = (const float4*)gam;
    const float4* b4 = (const float4*)bet;

    float4 v[6];
    float s = 0.f, sq = 0.f;
#pragma unroll
    for (int g = 0; g < 6; g++) {
        v[g] = row[lane + 32 * g];
        s += v[g].x + v[g].y + v[g].z + v[g].w;
        sq += v[g].x * v[g].x + v[g].y * v[g].y + v[g].z * v[g].z + v[g].w * v[g].w;
    }
    s = warp_sum(s);
    sq = warp_sum(sq);
    float mu = s * (1.0f / CC);
    float rstd = rsqrtf(sq * (1.0f / CC) - mu * mu + 1e-5f);

    float y[6][4];
    float m = 0.f;
#pragma unroll
    for (int g = 0; g < 6; g++) {
        float4 gg = g4[lane + 32 * g], bb = b4[lane + 32 * g];
        y[g][0] = (v[g].x - mu) * rstd * gg.x + bb.x;
        y[g][1] = (v[g].y - mu) * rstd * gg.y + bb.y;
        y[g][2] = (v[g].z - mu) * rstd * gg.z + bb.z;
        y[g][3] = (v[g].w - mu) * rstd * gg.w + bb.w;
#pragma unroll
        for (int e = 0; e < 4; e++) m = fmaxf(m, fabsf(y[g][e]));
    }
    m = warp_max(m);
    float sa = fmaxf(m, 1e-30f) * (1.0f / 127.0f);
    float inv = 1.0f / sa;
    if (lane == 0) g_asc[t] = sa;

    char4* d1 = (char4*)(g_aq1 + (size_t)t * CC);
    char4* d2 = (char4*)(g_aq2 + (size_t)t * CC);
#pragma unroll
    for (int g = 0; g < 6; g++) {
        char4 c1, c2;
        quant4(y[g], inv, c1, c2);
        d1[lane + 32 * g] = c1;
        d2[lane + 32 * g] = c2;
    }
}

// ---------------------------------------------------------------------------
// Weight prep: per-output-column max (parallel over k), then quantized
// transpose.
// ---------------------------------------------------------------------------
__global__ __launch_bounds__(256) void k_wmax(const float* __restrict__ w,
                                              int N, float* __restrict__ bsc) {
    __shared__ float red[8][33];
    int tx = threadIdx.x & 31, ks = threadIdx.x >> 5;
    int n = blockIdx.x * 32 + tx;
    float m = 0.0f;
    for (int k = ks; k < CC; k += 8)
        m = fmaxf(m, fabsf(w[(size_t)k * N + n]));
    red[ks][tx] = m;
    __syncthreads();
    if (ks == 0) {
        float v = red[0][tx];
#pragma unroll
        for (int i = 1; i < 8; i++) v = fmaxf(v, red[i][tx]);
        bsc[n] = fmaxf(v, 1e-30f) * (1.0f / 127.0f);
    }
}

__global__ __launch_bounds__(256) void k_wquant(const float* __restrict__ w,
                                                int N, const float* __restrict__ bsc,
                                                int8_t* __restrict__ q1,
                                                int8_t* __restrict__ q2) {
    __shared__ float t[32][33];
    int n0 = blockIdx.x * 32, k0 = blockIdx.y * 32;
    int tx = threadIdx.x & 31, ty = threadIdx.x >> 5;
    for (int i = ty; i < 32; i += 8) t[i][tx] = w[(size_t)(k0 + i) * N + n0 + tx];
    __syncthreads();
    for (int i = ty; i < 32; i += 8) {
        float v = t[tx][i];  // element (k0+tx, n0+i)
        int n = n0 + i;
        float inv = 1.0f / bsc[n];
        int a = __float2int_rn(v * inv);
        float r = fmaf(v, inv, -(float)a);
        int b = __float2int_rn(r * QSCL2);
        size_t o = (size_t)n * CC + k0 + tx;
        q1[o] = (int8_t)a;
        q2[o] = (int8_t)b;
    }
}

// ---------------------------------------------------------------------------
// INT8 IMMA GEMM: C[M,NT] = sa[m]*sb[n]*(accH + accM/254)
// CTA 64x128, BK=64, 3 stages, 2 CTAs/SM. 8 warps 2(M) x 4(N).
// ---------------------------------------------------------------------------
#define IBM 64
#define IBN 128
#define IBK 64
#define IPITCH 80
#define A_TILE (IBM * IPITCH)               // 5120
#define B_TILE (IBN * IPITCH)               // 10240
#define ISTAGE (2 * A_TILE + 2 * B_TILE)    // 30720
#define INSTG 3
#define IGSMEM (INSTG * ISTAGE)             // 92160 -> 2 CTAs/SM

template <int ROWS>
__device__ __forceinline__ void load_i8_tile(uint32_t dst,
                                             const int8_t* __restrict__ g,
                                             int row0, int kc, int tid) {
#pragma unroll
    for (int i = 0; i < ROWS / 64; i++) {
        int idx = tid + i * 256;
        int r = idx >> 2, seg = idx & 3;
        cpa16(dst + (uint32_t)(r * IPITCH + seg * 16),
              g + (size_t)(row0 + r) * CC + kc + seg * 16);
    }
}

__device__ __forceinline__ void load_chunk_i8(uint32_t st, int bm, int bn, int kc,
                                              int tid, const int8_t* Bq1,
                                              const int8_t* Bq2) {
    load_i8_tile<64>(st,                       g_aq1, bm, kc, tid);
    load_i8_tile<64>(st + A_TILE,              g_aq2, bm, kc, tid);
    load_i8_tile<128>(st + 2 * A_TILE,         Bq1,   bn, kc, tid);
    load_i8_tile<128>(st + 2 * A_TILE + B_TILE, Bq2,  bn, kc, tid);
}

template <int LDC_>
__global__ __launch_bounds__(256, 2) void k_gemm_i8(const int8_t* __restrict__ Bq1,
                                                    const int8_t* __restrict__ Bq2,
                                                    const float* __restrict__ bsc,
                                                    float* __restrict__ C) {
    extern __shared__ char dsm[];
    uint32_t sb = smem_u32(dsm);
    int tid = threadIdx.x, lane = tid & 31, wid = tid >> 5;
    int wm = wid >> 2, wn = wid & 3;          // 2 x 4 warp grid
    int bm = blockIdx.y * IBM, bn = blockIdx.x * IBN;
    const int kt = CC / IBK;                  // 12

    uint32_t lrow = (uint32_t)(lane & 15);
    uint32_t lboff = (uint32_t)((lane >> 4) * 16);

    int accH[2][4][4], accM[2][4][4];
#pragma unroll
    for (int i = 0; i < 2; i++)
#pragma unroll
        for (int j = 0; j < 4; j++)
#pragma unroll
            for (int r = 0; r < 4; r++) { accH[i][j][r] = 0; accM[i][j][r] = 0; }

    // prologue: chunks 0,1 into stages 0,1
    load_chunk_i8(sb, bm, bn, 0, tid, Bq1, Bq2);
    asm volatile("cp.async.commit_group;" ::: "memory");
    load_chunk_i8(sb + ISTAGE, bm, bn, IBK, tid, Bq1, Bq2);
    asm volatile("cp.async.commit_group;" ::: "memory");

    for (int c = 0; c < kt; c++) {
        if (c + 1 < kt)
            asm volatile("cp.async.wait_group 1;" ::: "memory");
        else
            asm volatile("cp.async.wait_group 0;" ::: "memory");
        __syncthreads();   // chunk c visible; all warps past stage (c+2)%3

        if (c + 2 < kt) {
            load_chunk_i8(sb + ((c + 2) % INSTG) * ISTAGE, bm, bn, (c + 2) * IBK,
                          tid, Bq1, Bq2);
            asm volatile("cp.async.commit_group;" ::: "memory");
        }

        uint32_t st = sb + (c % INSTG) * ISTAGE;
#pragma unroll
        for (int ks = 0; ks < 2; ks++) {
            uint32_t b1f[4][2], b2f[4][2];
#pragma unroll
            for (int p = 0; p < 2; p++) {
                uint32_t addr = st + 2 * A_TILE +
                                (uint32_t)(wn * 32 + p * 16 + lrow) * IPITCH +
                                (uint32_t)(ks * 32) + lboff;
                uint32_t r[4];
                ldsm4(r, addr);
                b1f[2 * p][0] = r[0]; b1f[2 * p][1] = r[2];
                b1f[2 * p + 1][0] = r[1]; b1f[2 * p + 1][1] = r[3];
                ldsm4(r, addr + B_TILE);
                b2f[2 * p][0] = r[0]; b2f[2 * p][1] = r[2];
                b2f[2 * p + 1][0] = r[1]; b2f[2 * p + 1][1] = r[3];
            }
#pragma unroll
            for (int mt = 0; mt < 2; mt++) {
                uint32_t a1[4], a2[4];
                uint32_t aaddr = st +
                                 (uint32_t)(wm * 32 + mt * 16 + lrow) * IPITCH +
                                 (uint32_t)(ks * 32) + lboff;
                ldsm4(a1, aaddr);
                ldsm4(a2, aaddr + A_TILE);
#pragma unroll
                for (int nt = 0; nt < 4; nt++) mma_s8(accH[mt][nt], a1, b1f[nt]);
#pragma unroll
                for (int nt = 0; nt < 4; nt++) mma_s8(accM[mt][nt], a1, b2f[nt]);
#pragma unroll
                for (int nt = 0; nt < 4; nt++) mma_s8(accM[mt][nt], a2, b1f[nt]);
            }
        }
    }

    // epilogue: dequantize and store fp32
#pragma unroll
    for (int mt = 0; mt < 2; mt++) {
        int r0 = bm + wm * 32 + mt * 16 + (lane >> 2);
        float sa0 = g_asc[r0], sa1 = g_asc[r0 + 8];
#pragma unroll
        for (int nt = 0; nt < 4; nt++) {
            int cidx = bn + wn * 32 + nt * 8 + (lane & 3) * 2;
            float sb0 = bsc[cidx], sb1 = bsc[cidx + 1];
            const int* h = accH[mt][nt];
            const int* m = accM[mt][nt];
            float v00 = sa0 * sb0 * ((float)h[0] + (float)m[0] * (1.0f / QSCL2));
            float v01 = sa0 * sb1 * ((float)h[1] + (float)m[1] * (1.0f / QSCL2));
            float v10 = sa1 * sb0 * ((float)h[2] + (float)m[2] * (1.0f / QSCL2));
            float v11 = sa1 * sb1 * ((float)h[3] + (float)m[3] * (1.0f / QSCL2));
            *(float2*)(C + (size_t)r0 * LDC_ + cidx) = make_float2(v00, v01);
            *(float2*)(C + (size_t)(r0 + 8) * LDC_ + cidx) = make_float2(v10, v11);
        }
    }
}

// ---------------------------------------------------------------------------
// warp-per-token inverse L2 norm of k. No barriers.
// ---------------------------------------------------------------------------
__global__ __launch_bounds__(256) void k_norms() {
    int lane = threadIdx.x & 31;
    int t = blockIdx.x * 8 + (threadIdx.x >> 5);
    const float4* krow = (const float4*)(g_qkv + (size_t)t * QKVD + EE);
    float sk = 0.f;
#pragma unroll
    for (int g = 0; g < 6; g++) {
        float4 k = krow[lane + 32 * g];
        sk += k.x * k.x + k.y * k.y + k.z * k.z + k.w * k.w;
    }
    sk = warp_sum(sk);
    if (lane == 0) g_kinv[t] = 1.0f / fmaxf(sqrtf(sk), 1e-12f);
}

// ---------------------------------------------------------------------------
// kv partial sums: kv[b,e] = sum_t phi_k[t,e] * v[t,e]. 64 chunks x 8 batches.
// ---------------------------------------------------------------------------
__global__ __launch_bounds__(256) void k_kvred() {
    int b = blockIdx.y;
    int chunk = blockIdx.x;  // 0..KVCH-1
    int tid = threadIdx.x;
    float a0 = 0.f, a1 = 0.f, a2 = 0.f;
    int t0 = b * NN + chunk * (NN / KVCH);
#pragma unroll 2
    for (int i = 0; i < NN / KVCH; i++) {
        const float* row = g_qkv + (size_t)(t0 + i) * QKVD;
        const float* kr = row + EE;
        const float* vr = row + 2 * EE;
        float ki = g_kinv[t0 + i];
        a0 += (kr[tid] * ki) * vr[tid];
        a1 += (kr[tid + 256] * ki) * vr[tid + 256];
        a2 += (kr[tid + 512] * ki) * vr[tid + 512];
    }
    float* dst = g_kvpart + ((size_t)chunk * BQ + b) * EE;
    dst[tid] = a0; dst[tid + 256] = a1; dst[tid + 512] = a2;
}

__global__ __launch_bounds__(256) void k_kvsum() {
    int i = blockIdx.x * 256 + threadIdx.x;
    float s = 0.f;
#pragma unroll
    for (int c = 0; c < KVCH; c++) s += g_kvpart[(size_t)c * BQ * EE + i];
    g_kv[i] = s;
}

// ---------------------------------------------------------------------------
// warp-per-token: qinv, attn = phi_q*kv, layernorm, int8 quant. No barriers.
// ---------------------------------------------------------------------------
__global__ __launch_bounds__(256) void k_attn_ln(const float* __restrict__ gam,
                                                 const float* __restrict__ bet) {
    int lane = threadIdx.x & 31;
    int t = blockIdx.x * 8 + (threadIdx.x >> 5);
    int b = t >> 12;
    const float4* qrow = (const float4*)(g_qkv + (size_t)t * QKVD);
    const float4* kvb = (const float4*)(g_kv + b * EE);
    const float4* g4 = (const float4*)gam;
    const float4* b4 = (const float4*)bet;

    float4 q[6];
    float qsq = 0.f;
#pragma unroll
    for (int g = 0; g < 6; g++) {
        q[g] = qrow[lane + 32 * g];
        qsq += q[g].x * q[g].x + q[g].y * q[g].y + q[g].z * q[g].z + q[g].w * q[g].w;
    }
    qsq = warp_sum(qsq);
    float qi = 1.0f / fmaxf(sqrtf(qsq), 1e-12f);

    float a[6][4];
    float s = 0.f, sq = 0.f;
#pragma unroll
    for (int g = 0; g < 6; g++) {
        float4 kv = kvb[lane + 32 * g];
        a[g][0] = (q[g].x * qi) * kv.x;
        a[g][1] = (q[g].y * qi) * kv.y;
        a[g][2] = (q[g].z * qi) * kv.z;
        a[g][3] = (q[g].w * qi) * kv.w;
#pragma unroll
        for (int e = 0; e < 4; e++) { s += a[g][e]; sq += a[g][e] * a[g][e]; }
    }
    s = warp_sum(s);
    sq = warp_sum(sq);
    float mu = s * (1.0f / EE);
    float rstd = rsqrtf(sq * (1.0f / EE) - mu * mu + 1e-5f);

    float y[6][4];
    float m = 0.f;
#pragma unroll
    for (int g = 0; g < 6; g++) {
        float4 gg = g4[lane + 32 * g], bb = b4[lane + 32 * g];
        y[g][0] = (a[g][0] - mu) * rstd * gg.x + bb.x;
        y[g][1] = (a[g][1] - mu) * rstd * gg.y + bb.y;
        y[g][2] = (a[g][2] - mu) * rstd * gg.z + bb.z;
        y[g][3] = (a[g][3] - mu) * rstd * gg.w + bb.w;
#pragma unroll
        for (int e = 0; e < 4; e++) m = fmaxf(m, fabsf(y[g][e]));
    }
    m = warp_max(m);
    float sa = fmaxf(m, 1e-30f) * (1.0f / 127.0f);
    float inv = 1.0f / sa;
    if (lane == 0) g_asc[t] = sa;

    char4* d1 = (char4*)(g_aq1 + (size_t)t * EE);
    char4* d2 = (char4*)(g_aq2 + (size_t)t * EE);
#pragma unroll
    for (int g = 0; g < 6; g++) {
        char4 c1, c2;
        quant4(y[g], inv, c1, c2);
        d1[lane + 32 * g] = c1;
        d2[lane + 32 * g] = c2;
    }
}

// ---------------------------------------------------------------------------
extern "C" void kernel_launch(void* const* d_in, const int* in_sizes, int n_in,
                              void* d_out, int out_size) {
    const float* x        = (const float*)d_in[0];
    const float* w_qkv    = (const float*)d_in[1];
    const float* w_proj   = (const float*)d_in[2];
    const float* ln_in_g  = (const float*)d_in[3];
    const float* ln_in_b  = (const float*)d_in[4];
    const float* ln_out_g = (const float*)d_in[5];
    const float* ln_out_b = (const float*)d_in[6];
    float* out = (float*)d_out;

    cudaFuncSetAttribute(k_gemm_i8<QKVD>, cudaFuncAttributeMaxDynamicSharedMemorySize, IGSMEM);
    cudaFuncSetAttribute(k_gemm_i8<CC>, cudaFuncAttributeMaxDynamicSharedMemorySize, IGSMEM);

    int8_t* bq1q; cudaGetSymbolAddress((void**)&bq1q, g_bq1q);
    int8_t* bq2q; cudaGetSymbolAddress((void**)&bq2q, g_bq2q);
    float*  bscq; cudaGetSymbolAddress((void**)&bscq, g_bscq);
    int8_t* bq1p; cudaGetSymbolAddress((void**)&bq1p, g_bq1p);
    int8_t* bq2p; cudaGetSymbolAddress((void**)&bq2p, g_bq2p);
    float*  bscp; cudaGetSymbolAddress((void**)&bscp, g_bscp);
    float*  qkv;  cudaGetSymbolAddress((void**)&qkv, g_qkv);

    // order chosen so k_gemm_i8<QKVD> is the 4th launch (ncu -s captures it)
    k_ln_in<<<MM / 8, 256>>>(x, ln_in_g, ln_in_b);
    k_wmax<<<QKVD / 32, 256>>>(w_qkv, QKVD, bscq);
    k_wquant<<<dim3(QKVD / 32, CC / 32), 256>>>(w_qkv, QKVD, bscq, bq1q, bq2q);
    k_gemm_i8<QKVD><<<dim3(QKVD / IBN, MM / IBM), 256, IGSMEM>>>(bq1q, bq2q, bscq, qkv);
    k_norms<<<MM / 8, 256>>>();
    k_kvred<<<dim3(KVCH, BQ), 256>>>();
    k_kvsum<<<BQ * EE / 256, 256>>>();
    k_attn_ln<<<MM / 8, 256>>>(ln_out_g, ln_out_b);
    k_wmax<<<CC / 32, 256>>>(w_proj, CC, bscp);
    k_wquant<<<dim3(CC / 32, CC / 32), 256>>>(w_proj, CC, bscp, bq1p, bq2p);
    k_gemm_i8<CC><<<dim3(CC / IBN, MM / IBM), 256, IGSMEM>>>(bq1p, bq2p, bscp, out);
}